// round 1
// baseline (speedup 1.0000x reference)
#include <cuda_runtime.h>
#include <math.h>

#define NC    16384
#define DIN   512
#define DH    1024
#define DOUT  512
#define MW    128
#define H3    (3*DH)

// ---------------- scratch (__device__ globals; no allocation allowed) ----------------
__device__ float g_Wcat[DH*256];            // [K=1024, N=256]  (Wa1_h | Wg1_h)
__device__ float g_bcat[256];               // ba1 + x@Wa1_x  |  bg1 + x@Wg1_x
__device__ float g_W2cat[256*DOUT];         // [K=256, N=512]  (Wa2 ; -Wg2)
__device__ float g_b2[DOUT];                // ba2 - bg2
__device__ float g_A1[(size_t)NC*256];      // relu layer-1 (actor|gating)
__device__ float g_out[(size_t)NC*DOUT];    // output = a - g
__device__ float g_tension[NC];
__device__ float g_gi[(size_t)NC*H3];       // out@W_ih[:512] + b_ih
__device__ float g_gh[(size_t)NC*H3];       // h@W_hh + b_hh
__device__ float g_h1[(size_t)NC*DH];       // post-GRU, post-mod/clip
__device__ float g_part_all[64*DH];
__device__ float g_part_pos[64*DH];
__device__ float g_part_neg[64*DH];
__device__ float g_fmean[8*DH];
__device__ float g_gop[DH];
__device__ float g_pm[DH];
__device__ float g_nm[DH];
__device__ int   g_cnt[18];                 // [0]=cnt_pos,[1]=cnt_neg,[2..9]=pos/faction,[10..17]=neg/faction
__device__ float g_soft[2];                 // [0]=max, [1]=sum(exp)
__device__ float g_wts[NC];                 // exp(t - max)
__device__ float g_partial[64*DOUT];

// ---------------- prep kernels ----------------
__global__ void prep_bcat(const float* __restrict__ x,
                          const float* __restrict__ Wa1, const float* __restrict__ ba1,
                          const float* __restrict__ Wg1, const float* __restrict__ bg1) {
    __shared__ float xs[DIN];
    int c = threadIdx.x;                    // 256
    for (int k = c; k < DIN; k += 256) xs[k] = x[k];
    __syncthreads();
    const float* W = (c < MW) ? Wa1 : Wg1;
    int cc = c & (MW-1);
    float s = (c < MW) ? ba1[cc] : bg1[cc];
    for (int k = 0; k < DIN; k++) s += xs[k] * W[k*MW + cc];
    g_bcat[c] = s;
}

__global__ void prep_wcat(const float* __restrict__ Wa1, const float* __restrict__ Wg1) {
    int idx = blockIdx.x*256 + threadIdx.x;   // DH*256
    int k = idx >> 8, c = idx & 255;
    g_Wcat[idx] = (c < MW) ? Wa1[(DIN + k)*MW + c] : Wg1[(DIN + k)*MW + (c - MW)];
}

__global__ void prep_w2(const float* __restrict__ Wa2, const float* __restrict__ ba2,
                        const float* __restrict__ Wg2, const float* __restrict__ bg2) {
    int idx = blockIdx.x*256 + threadIdx.x;   // 256*DOUT
    int k = idx >> 9, n = idx & 511;
    g_W2cat[idx] = (k < MW) ? Wa2[k*DOUT + n] : -Wg2[(k - MW)*DOUT + n];
    if (idx < DOUT) g_b2[idx] = ba2[idx] - bg2[idx];
}

__global__ void counts_k(const int* __restrict__ pos) {
    __shared__ int s[18];
    int tid = threadIdx.x;                    // 256
    if (tid < 18) s[tid] = 0;
    __syncthreads();
    for (int i = tid; i < NC; i += 256) {
        int p = pos[i], f = i >> 11;
        if (p > 0)      { atomicAdd(&s[0], 1); atomicAdd(&s[2+f], 1); }
        else if (p < 0) { atomicAdd(&s[1], 1); atomicAdd(&s[10+f], 1); }
    }
    __syncthreads();
    if (tid < 18) g_cnt[tid] = s[tid];
}

// ---------------- fp32 SGEMM: C[M,N] = A[M,K] @ B[K,N] + bias[N], optional relu ----------------
template <bool RELU>
__global__ __launch_bounds__(256) void sgemm128(const float* __restrict__ A,
                                                const float* __restrict__ B,
                                                const float* __restrict__ bias,
                                                float* __restrict__ C,
                                                int M, int N, int K) {
    const int BM = 128, BN = 128, BK = 16;
    __shared__ float As[BK][BM];
    __shared__ float Bs[BK][BN];
    int tid = threadIdx.x;
    int bx = blockIdx.x, by = blockIdx.y;
    const float* Ab = A + (size_t)by * BM * K;
    const float* Bb = B + (size_t)bx * BN;

    int trow = (tid >> 4) << 3;               // 0..120 step 8
    int tcol = (tid & 15) << 3;
    int aRow = tid >> 2;                      // 0..63
    int aCol = (tid & 3) << 2;                // 0,4,8,12
    int bRow = tid >> 5;                      // 0..7
    int bCol = (tid & 31) << 2;               // 0..124

    float acc[8][8];
#pragma unroll
    for (int m = 0; m < 8; m++)
#pragma unroll
        for (int n = 0; n < 8; n++) acc[m][n] = 0.f;

    for (int k0 = 0; k0 < K; k0 += BK) {
        float4 a0 = *(const float4*)(Ab + (size_t)aRow        * K + k0 + aCol);
        float4 a1 = *(const float4*)(Ab + (size_t)(aRow + 64) * K + k0 + aCol);
        float4 b0 = *(const float4*)(Bb + (size_t)(k0 + bRow)     * N + bCol);
        float4 b1 = *(const float4*)(Bb + (size_t)(k0 + bRow + 8) * N + bCol);
        As[aCol+0][aRow] = a0.x; As[aCol+1][aRow] = a0.y;
        As[aCol+2][aRow] = a0.z; As[aCol+3][aRow] = a0.w;
        As[aCol+0][aRow+64] = a1.x; As[aCol+1][aRow+64] = a1.y;
        As[aCol+2][aRow+64] = a1.z; As[aCol+3][aRow+64] = a1.w;
        *(float4*)&Bs[bRow][bCol]     = b0;
        *(float4*)&Bs[bRow+8][bCol]   = b1;
        __syncthreads();
#pragma unroll
        for (int kk = 0; kk < BK; kk++) {
            float ar[8], br[8];
#pragma unroll
            for (int m = 0; m < 8; m++) ar[m] = As[kk][trow + m];
#pragma unroll
            for (int n = 0; n < 8; n++) br[n] = Bs[kk][tcol + n];
#pragma unroll
            for (int m = 0; m < 8; m++)
#pragma unroll
                for (int n = 0; n < 8; n++) acc[m][n] += ar[m] * br[n];
        }
        __syncthreads();
    }
#pragma unroll
    for (int m = 0; m < 8; m++) {
#pragma unroll
        for (int n = 0; n < 8; n++) {
            float v = acc[m][n] + bias[(size_t)bx*BN + tcol + n];
            if (RELU) v = fmaxf(v, 0.f);
            C[((size_t)by*BM + trow + m) * N + (size_t)bx*BN + tcol + n] = v;
        }
    }
}

// ---------------- tension = mean(output^2, axis=-1) ----------------
__global__ void tension_k() {
    int i = blockIdx.x;
    int tid = threadIdx.x;                    // 128
    const float4* row = (const float4*)(g_out + (size_t)i * DOUT);
    float4 v = row[tid];
    float s = v.x*v.x + v.y*v.y + v.z*v.z + v.w*v.w;
#pragma unroll
    for (int o = 16; o > 0; o >>= 1) s += __shfl_xor_sync(0xffffffffu, s, o);
    __shared__ float ws[4];
    if ((tid & 31) == 0) ws[tid >> 5] = s;
    __syncthreads();
    if (tid == 0) g_tension[i] = (ws[0]+ws[1]+ws[2]+ws[3]) * (1.0f/DOUT);
}

// ---------------- GRU gates + wealth mod + clip ----------------
__global__ void gates_k(const float* __restrict__ h,
                        const float* __restrict__ Wih_t,   // W_ih row 512
                        const float* __restrict__ wealth) {
    int j = blockIdx.x*256 + threadIdx.x;     // 0..1023
    int i = blockIdx.y;
    size_t b = (size_t)i * H3;
    float t = g_tension[i];
    float gir = g_gi[b + j]        + t * Wih_t[j];
    float giz = g_gi[b + DH + j]   + t * Wih_t[DH + j];
    float gin = g_gi[b + 2*DH + j] + t * Wih_t[2*DH + j];
    float ghr = g_gh[b + j];
    float ghz = g_gh[b + DH + j];
    float ghn = g_gh[b + 2*DH + j];
    float r = 1.f / (1.f + expf(-(gir + ghr)));
    float z = 1.f / (1.f + expf(-(giz + ghz)));
    float n = tanhf(gin + r * ghn);
    float hv = h[(size_t)i*DH + j];
    float nh = (1.f - z) * n + z * hv;
    float w = fminf(fmaxf(wealth[i], 0.1f), 2.0f);
    nh = nh * (0.9f + 0.1f * w);
    nh = fminf(fmaxf(nh, -10.f), 10.f);
    g_h1[(size_t)i*DH + j] = nh;
}

// ---------------- per-column sums by (chunk of 256 rows) split by sign ----------------
__global__ void sums1_k(const int* __restrict__ pos) {
    int chunk = blockIdx.x;                   // 64
    int col = blockIdx.y*256 + threadIdx.x;
    float sa = 0.f, sp = 0.f, sn = 0.f;
    int base = chunk * 256;
    for (int r = 0; r < 256; r++) {
        int i = base + r;
        float v = g_h1[(size_t)i*DH + col];
        int p = pos[i];
        sa += v;
        if (p > 0) sp += v;
        else if (p < 0) sn += v;
    }
    g_part_all[chunk*DH + col] = sa;
    g_part_pos[chunk*DH + col] = sp;
    g_part_neg[chunk*DH + col] = sn;
}

// ---------------- group means + post-sync faction means + global op ----------------
__global__ void sums2_k() {
    int col = blockIdx.x*256 + threadIdx.x;
    int cp = g_cnt[0], cn = g_cnt[1];
    bool ap = cp >= 2, an = cn >= 2;
    float psum = 0.f, nsum = 0.f;
    for (int ch = 0; ch < 64; ch++) {
        psum += g_part_pos[ch*DH + col];
        nsum += g_part_neg[ch*DH + col];
    }
    float pm = psum / (float)(cp > 1 ? cp : 1);
    float nm = nsum / (float)(cn > 1 ? cn : 1);
    g_pm[col] = pm; g_nm[col] = nm;
    float gop = 0.f;
    for (int f = 0; f < 8; f++) {
        float a = 0.f, p = 0.f, nn = 0.f;
        for (int c = 0; c < 8; c++) {
            int ch = f*8 + c;
            a  += g_part_all[ch*DH + col];
            p  += g_part_pos[ch*DH + col];
            nn += g_part_neg[ch*DH + col];
        }
        float s = a;
        if (ap) s += -0.1f * p  + 0.1f * (float)g_cnt[2+f]  * pm;
        if (an) s += -0.1f * nn + 0.1f * (float)g_cnt[10+f] * nm;
        float fm = s * (1.f/2048.f);
        g_fmean[f*DH + col] = fm;
        gop += fm;
    }
    g_gop[col] = gop * 0.125f;
}

// ---------------- final blend -> d_out[new_h] ----------------
__global__ void blend_k(const int* __restrict__ pos, const int* __restrict__ step_p,
                        float* __restrict__ outh) {
    int j = blockIdx.x*256 + threadIdx.x;
    int i = blockIdx.y;
    float h2 = g_h1[(size_t)i*DH + j];
    int p = pos[i];
    if (p > 0 && g_cnt[0] >= 2)      h2 = 0.9f*h2 + 0.1f*g_pm[j];
    else if (p < 0 && g_cnt[1] >= 2) h2 = 0.9f*h2 + 0.1f*g_nm[j];
    int f = i >> 11;
    float h3 = 0.85f*h2 + 0.15f*g_fmean[f*DH + j];
    if ((i & 2047) < 512 && step_p[0] > 5) h3 = 0.85f*h3 + 0.15f*g_gop[j];
    outh[(size_t)i*DH + j] = h3;
}

// ---------------- softmax stats + avg tension ----------------
__global__ void smax_k(float* __restrict__ out, int avg_off) {
    int tid = threadIdx.x;                    // 1024
    float m = -3.4e38f;
    for (int i = tid; i < NC; i += 1024) m = fmaxf(m, g_tension[i]);
#pragma unroll
    for (int o = 16; o > 0; o >>= 1) m = fmaxf(m, __shfl_xor_sync(0xffffffffu, m, o));
    __shared__ float red[32];
    if ((tid & 31) == 0) red[tid >> 5] = m;
    __syncthreads();
    if (tid < 32) {
        float v = red[tid];
#pragma unroll
        for (int o = 16; o > 0; o >>= 1) v = fmaxf(v, __shfl_xor_sync(0xffffffffu, v, o));
        if (tid == 0) red[0] = v;
    }
    __syncthreads();
    float mm = red[0];
    __syncthreads();
    float se = 0.f, st = 0.f;
    for (int i = tid; i < NC; i += 1024) {
        float t = g_tension[i];
        st += t;
        float e = expf(t - mm);
        se += e;
        g_wts[i] = e;
    }
#pragma unroll
    for (int o = 16; o > 0; o >>= 1) {
        se += __shfl_xor_sync(0xffffffffu, se, o);
        st += __shfl_xor_sync(0xffffffffu, st, o);
    }
    __shared__ float r2[32], r3[32];
    if ((tid & 31) == 0) { r2[tid >> 5] = se; r3[tid >> 5] = st; }
    __syncthreads();
    if (tid == 0) {
        float a = 0.f, b = 0.f;
        for (int w = 0; w < 32; w++) { a += r2[w]; b += r3[w]; }
        g_soft[0] = mm; g_soft[1] = a;
        out[avg_off] = b * (1.f/NC);
    }
}

__global__ void wsum_k() {
    int j = threadIdx.x;                      // 512
    int b = blockIdx.x;                       // 64
    float s = 0.f;
    int base = b * 256;
    for (int r = 0; r < 256; r++) {
        int i = base + r;
        s += g_wts[i] * g_out[(size_t)i*DOUT + j];
    }
    g_partial[b*DOUT + j] = s;
}

__global__ void pred_k(const float* __restrict__ Wo, const float* __restrict__ bo,
                       float* __restrict__ out) {
    __shared__ float comb[DOUT];
    int j = threadIdx.x;                      // 512
    float s = 0.f;
    for (int b = 0; b < 64; b++) s += g_partial[b*DOUT + j];
    comb[j] = s / g_soft[1];
    __syncthreads();
    float p = bo[j];
    for (int k = 0; k < DOUT; k++) p += comb[k] * Wo[k*DOUT + j];
    out[j] = p;
}

// ---------------- launch ----------------
extern "C" void kernel_launch(void* const* d_in, const int* in_sizes, int n_in,
                              void* d_out, int out_size) {
    const float* x       = (const float*)d_in[0];
    const float* hiddens = (const float*)d_in[1];
    const float* wealth  = (const float*)d_in[2];
    const float* Wa1     = (const float*)d_in[3];
    const float* ba1     = (const float*)d_in[4];
    const float* Wa2     = (const float*)d_in[5];
    const float* ba2     = (const float*)d_in[6];
    const float* Wg1     = (const float*)d_in[7];
    const float* bg1     = (const float*)d_in[8];
    const float* Wg2     = (const float*)d_in[9];
    const float* bg2     = (const float*)d_in[10];
    const float* W_ih    = (const float*)d_in[11];
    const float* W_hh    = (const float*)d_in[12];
    const float* b_ih    = (const float*)d_in[13];
    const float* b_hh    = (const float*)d_in[14];
    const float* Wo      = (const float*)d_in[15];
    const float* bo      = (const float*)d_in[16];
    const int*   pos     = (const int*)d_in[17];
    const int*   step    = (const int*)d_in[18];
    float* out = (float*)d_out;

    size_t newh_off = (size_t)out_size - (size_t)NC * DH;   // pred, avg_tension, new_h
    int avg_off = (int)(newh_off - 1);

    float *dWcat, *dbcat, *dW2, *db2, *dA1, *dOut, *dGi, *dGh;
    cudaGetSymbolAddress((void**)&dWcat, g_Wcat);
    cudaGetSymbolAddress((void**)&dbcat, g_bcat);
    cudaGetSymbolAddress((void**)&dW2,   g_W2cat);
    cudaGetSymbolAddress((void**)&db2,   g_b2);
    cudaGetSymbolAddress((void**)&dA1,   g_A1);
    cudaGetSymbolAddress((void**)&dOut,  g_out);
    cudaGetSymbolAddress((void**)&dGi,   g_gi);
    cudaGetSymbolAddress((void**)&dGh,   g_gh);

    // prep
    prep_bcat<<<1, 256>>>(x, Wa1, ba1, Wg1, bg1);
    prep_wcat<<<DH, 256>>>(Wa1, Wg1);
    prep_w2<<<(256*DOUT)/256, 256>>>(Wa2, ba2, Wg2, bg2);
    counts_k<<<1, 256>>>(pos);

    // G1: A1G1 = relu(h @ Wcat + bcat)   [16384, 256]
    sgemm128<true><<<dim3(256/128, NC/128), 256>>>(hiddens, dWcat, dbcat, dA1, NC, 256, DH);
    // G2: output = A1G1 @ W2cat + (ba2 - bg2)   [16384, 512]
    sgemm128<false><<<dim3(DOUT/128, NC/128), 256>>>(dA1, dW2, db2, dOut, NC, DOUT, 256);
    // tension
    tension_k<<<NC, 128>>>();
    // G3: gi = output @ W_ih[:512] + b_ih   [16384, 3072]
    sgemm128<false><<<dim3(H3/128, NC/128), 256>>>(dOut, W_ih, b_ih, dGi, NC, H3, DOUT);
    // G4: gh = h @ W_hh + b_hh   [16384, 3072]
    sgemm128<false><<<dim3(H3/128, NC/128), 256>>>(hiddens, W_hh, b_hh, dGh, NC, H3, DH);
    // gates
    gates_k<<<dim3(DH/256, NC), 256>>>(hiddens, W_ih + (size_t)DIN*H3, wealth);
    // sync reductions
    sums1_k<<<dim3(64, DH/256), 256>>>(pos);
    sums2_k<<<DH/256, 256>>>();
    // final blend -> new_h
    blend_k<<<dim3(DH/256, NC), 256>>>(pos, step, out + newh_off);
    // softmax + weighted combine + pred
    smax_k<<<1, 1024>>>(out, avg_off);
    wsum_k<<<64, DOUT>>>();
    pred_k<<<1, DOUT>>>(Wo, bo, out);
}

// round 2
// speedup vs baseline: 2.1654x; 2.1654x over previous
#include <cuda_runtime.h>
#include <math.h>
#include <stdint.h>

#define NC    16384
#define DIN   512
#define DH    1024
#define DOUT  512
#define MW    128
#define H3    (3*DH)

// ---------------- scratch (__device__ globals; no allocation allowed) ----------------
__device__ float g_Wcat[DH*256];            // [K=1024, N=256]  (Wa1_h | Wg1_h)
__device__ float g_bcat[256];               // ba1 + x@Wa1_x  |  bg1 + x@Wg1_x
__device__ float g_W2cat[256*DOUT];         // [K=256, N=512]  (Wa2 ; -Wg2)
__device__ float g_b2[DOUT];                // ba2 - bg2
__device__ float g_A1[(size_t)NC*256];      // relu layer-1 (actor|gating)
__device__ float g_out[(size_t)NC*DOUT];    // output = a - g
__device__ float g_tension[NC];
__device__ float g_gi[(size_t)NC*H3];       // out@W_ih[:512] + b_ih
__device__ float g_gh[(size_t)NC*H3];       // h@W_hh + b_hh
__device__ float g_h1[(size_t)NC*DH];       // post-GRU, post-mod/clip
__device__ float g_part_all[64*DH];
__device__ float g_part_pos[64*DH];
__device__ float g_part_neg[64*DH];
__device__ float g_fmean[8*DH];
__device__ float g_gop[DH];
__device__ float g_pm[DH];
__device__ float g_nm[DH];
__device__ int   g_cnt[18];                 // [0]=cnt_pos,[1]=cnt_neg,[2..9]=pos/faction,[10..17]=neg/faction
__device__ float g_soft[2];                 // [0]=max, [1]=sum(exp)
__device__ float g_wts[NC];                 // exp(t - max)
__device__ float g_partial[64*DOUT];

// ---------------- tf32 helpers ----------------
__device__ __forceinline__ uint32_t f2tf(float f) {
    uint32_t u; asm("cvt.rna.tf32.f32 %0, %1;" : "=r"(u) : "f"(f)); return u;
}

__device__ __forceinline__ void mma8(float* c, const uint32_t* a, const uint32_t* b) {
    asm volatile("mma.sync.aligned.m16n8k8.row.col.f32.tf32.tf32.f32 "
        "{%0,%1,%2,%3}, {%4,%5,%6,%7}, {%8,%9}, {%0,%1,%2,%3};"
        : "+f"(c[0]), "+f"(c[1]), "+f"(c[2]), "+f"(c[3])
        : "r"(a[0]), "r"(a[1]), "r"(a[2]), "r"(a[3]), "r"(b[0]), "r"(b[1]));
}

// ---------------- prep kernels ----------------
__global__ void prep_bcat(const float* __restrict__ x,
                          const float* __restrict__ Wa1, const float* __restrict__ ba1,
                          const float* __restrict__ Wg1, const float* __restrict__ bg1) {
    __shared__ float xs[DIN];
    int c = threadIdx.x;                    // 256
    for (int k = c; k < DIN; k += 256) xs[k] = x[k];
    __syncthreads();
    const float* W = (c < MW) ? Wa1 : Wg1;
    int cc = c & (MW-1);
    float s = (c < MW) ? ba1[cc] : bg1[cc];
    for (int k = 0; k < DIN; k++) s += xs[k] * W[k*MW + cc];
    g_bcat[c] = s;
}

__global__ void prep_wcat(const float* __restrict__ Wa1, const float* __restrict__ Wg1) {
    int idx = blockIdx.x*256 + threadIdx.x;   // DH*256
    int k = idx >> 8, c = idx & 255;
    g_Wcat[idx] = (c < MW) ? Wa1[(DIN + k)*MW + c] : Wg1[(DIN + k)*MW + (c - MW)];
}

__global__ void prep_w2(const float* __restrict__ Wa2, const float* __restrict__ ba2,
                        const float* __restrict__ Wg2, const float* __restrict__ bg2) {
    int idx = blockIdx.x*256 + threadIdx.x;   // 256*DOUT
    int k = idx >> 9, n = idx & 511;
    g_W2cat[idx] = (k < MW) ? Wa2[k*DOUT + n] : -Wg2[(k - MW)*DOUT + n];
    if (idx < DOUT) g_b2[idx] = ba2[idx] - bg2[idx];
    if (idx < 18) g_cnt[idx] = 0;
}

__global__ void counts_k(const int* __restrict__ pos) {
    __shared__ int s[18];
    int tid = threadIdx.x;                    // 256, grid 64
    if (tid < 18) s[tid] = 0;
    __syncthreads();
    int i = blockIdx.x*256 + tid;
    int p = pos[i], f = i >> 11;
    if (p > 0)      { atomicAdd(&s[0], 1); atomicAdd(&s[2+f], 1); }
    else if (p < 0) { atomicAdd(&s[1], 1); atomicAdd(&s[10+f], 1); }
    __syncthreads();
    if (tid < 18 && s[tid]) atomicAdd(&g_cnt[tid], s[tid]);
}

// ---------------- tf32 tensor-core GEMM: C[M,N] = A[M,K] @ B[K,N] + bias[N] ----------------
// 128x128 block tile, BK=32, 8 warps each 64x32, mma.sync m16n8k8 tf32
template <bool RELU>
__global__ __launch_bounds__(256) void tgemm(const float* __restrict__ A,
                                             const float* __restrict__ B,
                                             const float* __restrict__ bias,
                                             float* __restrict__ C,
                                             int M, int N, int K) {
    __shared__ uint32_t As[32*136];
    __shared__ uint32_t Bs[32*136];
    int tid = threadIdx.x;
    int warp = tid >> 5, lane = tid & 31;
    int go = lane >> 2, tig = lane & 3;
    int wm = warp >> 2, wn = warp & 3;
    int by = blockIdx.y, bx = blockIdx.x;
    const float* Ab = A + (size_t)(by * 128) * K;
    const float* Bb = B + (size_t)bx * 128;

    float acc[4][4][4];
#pragma unroll
    for (int mt = 0; mt < 4; mt++)
#pragma unroll
        for (int nt = 0; nt < 4; nt++)
#pragma unroll
            for (int q = 0; q < 4; q++) acc[mt][nt][q] = 0.f;

    int am = tid & 127;
    int kh = (tid >> 7) * 16;
    int bk = tid >> 3;
    int bn = (tid & 7) * 4;

    for (int k0 = 0; k0 < K; k0 += 32) {
        // A tile -> As[k][m], transposed, tf32-converted
        const float* ap = Ab + (size_t)am * K + k0 + kh;
#pragma unroll
        for (int j = 0; j < 4; j++) {
            float4 v = *(const float4*)(ap + 4*j);
            As[(kh + 4*j + 0)*136 + am] = f2tf(v.x);
            As[(kh + 4*j + 1)*136 + am] = f2tf(v.y);
            As[(kh + 4*j + 2)*136 + am] = f2tf(v.z);
            As[(kh + 4*j + 3)*136 + am] = f2tf(v.w);
        }
        // B tile -> Bs[k][n]
        const float* bp = Bb + (size_t)(k0 + bk) * N + bn;
#pragma unroll
        for (int j = 0; j < 4; j++) {
            float4 v = *(const float4*)(bp + 32*j);
            uint32_t* d = &Bs[bk*136 + bn + 32*j];
            d[0] = f2tf(v.x); d[1] = f2tf(v.y); d[2] = f2tf(v.z); d[3] = f2tf(v.w);
        }
        __syncthreads();
#pragma unroll
        for (int kk = 0; kk < 32; kk += 8) {
            uint32_t a[4][4], b[4][2];
#pragma unroll
            for (int mt = 0; mt < 4; mt++) {
                int ar = wm*64 + mt*16 + go;
                a[mt][0] = As[(kk + tig)*136 + ar];
                a[mt][1] = As[(kk + tig)*136 + ar + 8];
                a[mt][2] = As[(kk + tig + 4)*136 + ar];
                a[mt][3] = As[(kk + tig + 4)*136 + ar + 8];
            }
#pragma unroll
            for (int nt = 0; nt < 4; nt++) {
                int bc = wn*32 + nt*8 + go;
                b[nt][0] = Bs[(kk + tig)*136 + bc];
                b[nt][1] = Bs[(kk + tig + 4)*136 + bc];
            }
#pragma unroll
            for (int mt = 0; mt < 4; mt++)
#pragma unroll
                for (int nt = 0; nt < 4; nt++)
                    mma8(acc[mt][nt], a[mt], b[nt]);
        }
        __syncthreads();
    }
    // epilogue: bias (+relu), write
#pragma unroll
    for (int mt = 0; mt < 4; mt++) {
        int r0 = by*128 + wm*64 + mt*16 + go;
#pragma unroll
        for (int nt = 0; nt < 4; nt++) {
            int c = bx*128 + wn*32 + nt*8 + tig*2;
            float b0v = bias[c], b1v = bias[c+1];
            float v0 = acc[mt][nt][0] + b0v;
            float v1 = acc[mt][nt][1] + b1v;
            float v2 = acc[mt][nt][2] + b0v;
            float v3 = acc[mt][nt][3] + b1v;
            if (RELU) {
                v0 = fmaxf(v0, 0.f); v1 = fmaxf(v1, 0.f);
                v2 = fmaxf(v2, 0.f); v3 = fmaxf(v3, 0.f);
            }
            float2 lo = make_float2(v0, v1);
            float2 hi = make_float2(v2, v3);
            *(float2*)&C[(size_t)r0 * N + c]       = lo;
            *(float2*)&C[(size_t)(r0 + 8) * N + c] = hi;
        }
    }
}

// ---------------- tension = mean(output^2, axis=-1) ----------------
__global__ void tension_k() {
    int i = blockIdx.x;
    int tid = threadIdx.x;                    // 128
    const float4* row = (const float4*)(g_out + (size_t)i * DOUT);
    float4 v = row[tid];
    float s = v.x*v.x + v.y*v.y + v.z*v.z + v.w*v.w;
#pragma unroll
    for (int o = 16; o > 0; o >>= 1) s += __shfl_xor_sync(0xffffffffu, s, o);
    __shared__ float ws[4];
    if ((tid & 31) == 0) ws[tid >> 5] = s;
    __syncthreads();
    if (tid == 0) g_tension[i] = (ws[0]+ws[1]+ws[2]+ws[3]) * (1.0f/DOUT);
}

// ---------------- GRU gates + wealth mod + clip ----------------
__global__ void gates_k(const float* __restrict__ h,
                        const float* __restrict__ Wih_t,   // W_ih row 512
                        const float* __restrict__ wealth) {
    int j = blockIdx.x*256 + threadIdx.x;     // 0..1023
    int i = blockIdx.y;
    size_t b = (size_t)i * H3;
    float t = g_tension[i];
    float gir = g_gi[b + j]        + t * Wih_t[j];
    float giz = g_gi[b + DH + j]   + t * Wih_t[DH + j];
    float gin = g_gi[b + 2*DH + j] + t * Wih_t[2*DH + j];
    float ghr = g_gh[b + j];
    float ghz = g_gh[b + DH + j];
    float ghn = g_gh[b + 2*DH + j];
    float r = 1.f / (1.f + expf(-(gir + ghr)));
    float z = 1.f / (1.f + expf(-(giz + ghz)));
    float n = tanhf(gin + r * ghn);
    float hv = h[(size_t)i*DH + j];
    float nh = (1.f - z) * n + z * hv;
    float w = fminf(fmaxf(wealth[i], 0.1f), 2.0f);
    nh = nh * (0.9f + 0.1f * w);
    nh = fminf(fmaxf(nh, -10.f), 10.f);
    g_h1[(size_t)i*DH + j] = nh;
}

// ---------------- per-column sums by (chunk of 256 rows) split by sign ----------------
__global__ void sums1_k(const int* __restrict__ pos) {
    int chunk = blockIdx.x;                   // 64
    int col = blockIdx.y*256 + threadIdx.x;
    float sa = 0.f, sp = 0.f, sn = 0.f;
    int base = chunk * 256;
    for (int r = 0; r < 256; r++) {
        int i = base + r;
        float v = g_h1[(size_t)i*DH + col];
        int p = pos[i];
        sa += v;
        if (p > 0) sp += v;
        else if (p < 0) sn += v;
    }
    g_part_all[chunk*DH + col] = sa;
    g_part_pos[chunk*DH + col] = sp;
    g_part_neg[chunk*DH + col] = sn;
}

// ---------------- group means + post-sync faction means + global op ----------------
__global__ void sums2_k() {
    int col = blockIdx.x*256 + threadIdx.x;
    int cp = g_cnt[0], cn = g_cnt[1];
    bool ap = cp >= 2, an = cn >= 2;
    float psum = 0.f, nsum = 0.f;
    for (int ch = 0; ch < 64; ch++) {
        psum += g_part_pos[ch*DH + col];
        nsum += g_part_neg[ch*DH + col];
    }
    float pm = psum / (float)(cp > 1 ? cp : 1);
    float nm = nsum / (float)(cn > 1 ? cn : 1);
    g_pm[col] = pm; g_nm[col] = nm;
    float gop = 0.f;
    for (int f = 0; f < 8; f++) {
        float a = 0.f, p = 0.f, nn = 0.f;
        for (int c = 0; c < 8; c++) {
            int ch = f*8 + c;
            a  += g_part_all[ch*DH + col];
            p  += g_part_pos[ch*DH + col];
            nn += g_part_neg[ch*DH + col];
        }
        float s = a;
        if (ap) s += -0.1f * p  + 0.1f * (float)g_cnt[2+f]  * pm;
        if (an) s += -0.1f * nn + 0.1f * (float)g_cnt[10+f] * nm;
        float fm = s * (1.f/2048.f);
        g_fmean[f*DH + col] = fm;
        gop += fm;
    }
    g_gop[col] = gop * 0.125f;
}

// ---------------- final blend -> d_out[new_h] ----------------
__global__ void blend_k(const int* __restrict__ pos, const int* __restrict__ step_p,
                        float* __restrict__ outh) {
    int j = blockIdx.x*256 + threadIdx.x;
    int i = blockIdx.y;
    float h2 = g_h1[(size_t)i*DH + j];
    int p = pos[i];
    if (p > 0 && g_cnt[0] >= 2)      h2 = 0.9f*h2 + 0.1f*g_pm[j];
    else if (p < 0 && g_cnt[1] >= 2) h2 = 0.9f*h2 + 0.1f*g_nm[j];
    int f = i >> 11;
    float h3 = 0.85f*h2 + 0.15f*g_fmean[f*DH + j];
    if ((i & 2047) < 512 && step_p[0] > 5) h3 = 0.85f*h3 + 0.15f*g_gop[j];
    outh[(size_t)i*DH + j] = h3;
}

// ---------------- softmax stats + avg tension ----------------
__global__ void smax_k(float* __restrict__ out, int avg_off) {
    int tid = threadIdx.x;                    // 1024
    float m = -3.4e38f;
    for (int i = tid; i < NC; i += 1024) m = fmaxf(m, g_tension[i]);
#pragma unroll
    for (int o = 16; o > 0; o >>= 1) m = fmaxf(m, __shfl_xor_sync(0xffffffffu, m, o));
    __shared__ float red[32];
    if ((tid & 31) == 0) red[tid >> 5] = m;
    __syncthreads();
    if (tid < 32) {
        float v = red[tid];
#pragma unroll
        for (int o = 16; o > 0; o >>= 1) v = fmaxf(v, __shfl_xor_sync(0xffffffffu, v, o));
        if (tid == 0) red[0] = v;
    }
    __syncthreads();
    float mm = red[0];
    __syncthreads();
    float se = 0.f, st = 0.f;
    for (int i = tid; i < NC; i += 1024) {
        float t = g_tension[i];
        st += t;
        float e = expf(t - mm);
        se += e;
        g_wts[i] = e;
    }
#pragma unroll
    for (int o = 16; o > 0; o >>= 1) {
        se += __shfl_xor_sync(0xffffffffu, se, o);
        st += __shfl_xor_sync(0xffffffffu, st, o);
    }
    __shared__ float r2[32], r3[32];
    if ((tid & 31) == 0) { r2[tid >> 5] = se; r3[tid >> 5] = st; }
    __syncthreads();
    if (tid == 0) {
        float a = 0.f, b = 0.f;
        for (int w = 0; w < 32; w++) { a += r2[w]; b += r3[w]; }
        g_soft[0] = mm; g_soft[1] = a;
        out[avg_off] = b * (1.f/NC);
    }
}

__global__ void wsum_k() {
    int j = threadIdx.x;                      // 512
    int b = blockIdx.x;                       // 64
    float s = 0.f;
    int base = b * 256;
    for (int r = 0; r < 256; r++) {
        int i = base + r;
        s += g_wts[i] * g_out[(size_t)i*DOUT + j];
    }
    g_partial[b*DOUT + j] = s;
}

__global__ void pred_k(const float* __restrict__ Wo, const float* __restrict__ bo,
                       float* __restrict__ out) {
    __shared__ float comb[DOUT];
    int j = threadIdx.x;                      // 512
    float s = 0.f;
    for (int b = 0; b < 64; b++) s += g_partial[b*DOUT + j];
    comb[j] = s / g_soft[1];
    __syncthreads();
    float p = bo[j];
    for (int k = 0; k < DOUT; k++) p += comb[k] * Wo[k*DOUT + j];
    out[j] = p;
}

// ---------------- launch ----------------
extern "C" void kernel_launch(void* const* d_in, const int* in_sizes, int n_in,
                              void* d_out, int out_size) {
    const float* x       = (const float*)d_in[0];
    const float* hiddens = (const float*)d_in[1];
    const float* wealth  = (const float*)d_in[2];
    const float* Wa1     = (const float*)d_in[3];
    const float* ba1     = (const float*)d_in[4];
    const float* Wa2     = (const float*)d_in[5];
    const float* ba2     = (const float*)d_in[6];
    const float* Wg1     = (const float*)d_in[7];
    const float* bg1     = (const float*)d_in[8];
    const float* Wg2     = (const float*)d_in[9];
    const float* bg2     = (const float*)d_in[10];
    const float* W_ih    = (const float*)d_in[11];
    const float* W_hh    = (const float*)d_in[12];
    const float* b_ih    = (const float*)d_in[13];
    const float* b_hh    = (const float*)d_in[14];
    const float* Wo      = (const float*)d_in[15];
    const float* bo      = (const float*)d_in[16];
    const int*   pos     = (const int*)d_in[17];
    const int*   step    = (const int*)d_in[18];
    float* out = (float*)d_out;

    size_t newh_off = (size_t)out_size - (size_t)NC * DH;   // pred, avg_tension, new_h
    int avg_off = (int)(newh_off - 1);

    float *dWcat, *dbcat, *dW2, *db2, *dA1, *dOut, *dGi, *dGh;
    cudaGetSymbolAddress((void**)&dWcat, g_Wcat);
    cudaGetSymbolAddress((void**)&dbcat, g_bcat);
    cudaGetSymbolAddress((void**)&dW2,   g_W2cat);
    cudaGetSymbolAddress((void**)&db2,   g_b2);
    cudaGetSymbolAddress((void**)&dA1,   g_A1);
    cudaGetSymbolAddress((void**)&dOut,  g_out);
    cudaGetSymbolAddress((void**)&dGi,   g_gi);
    cudaGetSymbolAddress((void**)&dGh,   g_gh);

    // prep
    prep_bcat<<<1, 256>>>(x, Wa1, ba1, Wg1, bg1);
    prep_wcat<<<DH, 256>>>(Wa1, Wg1);
    prep_w2<<<(256*DOUT)/256, 256>>>(Wa2, ba2, Wg2, bg2);
    counts_k<<<64, 256>>>(pos);

    // G1: A1G1 = relu(h @ Wcat + bcat)   [16384, 256]
    tgemm<true><<<dim3(256/128, NC/128), 256>>>(hiddens, dWcat, dbcat, dA1, NC, 256, DH);
    // G2: output = A1G1 @ W2cat + (ba2 - bg2)   [16384, 512]
    tgemm<false><<<dim3(DOUT/128, NC/128), 256>>>(dA1, dW2, db2, dOut, NC, DOUT, 256);
    // tension
    tension_k<<<NC, 128>>>();
    // G3: gi = output @ W_ih[:512] + b_ih   [16384, 3072]
    tgemm<false><<<dim3(H3/128, NC/128), 256>>>(dOut, W_ih, b_ih, dGi, NC, H3, DOUT);
    // G4: gh = h @ W_hh + b_hh   [16384, 3072]
    tgemm<false><<<dim3(H3/128, NC/128), 256>>>(hiddens, W_hh, b_hh, dGh, NC, H3, DH);
    // gates
    gates_k<<<dim3(DH/256, NC), 256>>>(hiddens, W_ih + (size_t)DIN*H3, wealth);
    // sync reductions
    sums1_k<<<dim3(64, DH/256), 256>>>(pos);
    sums2_k<<<DH/256, 256>>>();
    // final blend -> new_h
    blend_k<<<dim3(DH/256, NC), 256>>>(pos, step, out + newh_off);
    // softmax + weighted combine + pred
    smax_k<<<1, 1024>>>(out, avg_off);
    wsum_k<<<64, DOUT>>>();
    pred_k<<<1, DOUT>>>(Wo, bo, out);
}

// round 7
// speedup vs baseline: 2.2496x; 1.0388x over previous
#include <cuda_runtime.h>
#include <math.h>
#include <stdint.h>

#define NC    16384
#define DIN   512
#define DH    1024
#define DOUT  512
#define MW    128
#define H3    (3*DH)

// ---------------- scratch (__device__ globals) ----------------
__device__ float g_Wcat[DH*256];            // [K=1024][N=256] tf32-rounded
__device__ float g_bcat[256];
__device__ float g_W2cat[256*DOUT];         // [K=256][N=512] tf32-rounded (Wa2 ; -Wg2)
__device__ float g_b2[DOUT];
__device__ float g_WihR[(size_t)DOUT*H3];   // rounded W_ih[0:512]
__device__ float g_WhhR[(size_t)DH*H3];     // rounded W_hh
__device__ float g_hr[(size_t)NC*DH];       // rounded hiddens
__device__ float g_A1[(size_t)NC*256];      // relu layer-1 (rounded)
__device__ float g_out[(size_t)NC*DOUT];    // exact output = a - g
__device__ float g_outr[(size_t)NC*DOUT];   // rounded copy for G3
__device__ float g_tension[NC];
__device__ float g_gi[(size_t)NC*H3];
__device__ float g_gh[(size_t)NC*H3];
__device__ float g_h1[(size_t)NC*DH];
__device__ float g_part_all[64*DH];
__device__ float g_part_pos[64*DH];
__device__ float g_part_neg[64*DH];
__device__ float g_fmean[8*DH];
__device__ float g_gop[DH];
__device__ float g_pm[DH];
__device__ float g_nm[DH];
__device__ int   g_cnt[18];
__device__ float g_soft[2];
__device__ float g_wts[NC];
__device__ float g_partial[64*DOUT];

// ---------------- helpers ----------------
__device__ __forceinline__ uint32_t f2tf(float f) {
    uint32_t u; asm("cvt.rna.tf32.f32 %0, %1;" : "=r"(u) : "f"(f)); return u;
}
__device__ __forceinline__ float rnatf(float f) { return __uint_as_float(f2tf(f)); }

__device__ __forceinline__ void mma8(float* c, const uint32_t* a, const uint32_t* b) {
    asm volatile("mma.sync.aligned.m16n8k8.row.col.f32.tf32.tf32.f32 "
        "{%0,%1,%2,%3}, {%4,%5,%6,%7}, {%8,%9}, {%0,%1,%2,%3};"
        : "+f"(c[0]), "+f"(c[1]), "+f"(c[2]), "+f"(c[3])
        : "r"(a[0]), "r"(a[1]), "r"(a[2]), "r"(a[3]), "r"(b[0]), "r"(b[1]));
}

__device__ __forceinline__ uint32_t s2u(const void* p) {
    uint32_t a;
    asm("{ .reg .u64 t; cvta.to.shared.u64 t, %1; cvt.u32.u64 %0, t; }" : "=r"(a) : "l"(p));
    return a;
}

// ---------------- prep kernels ----------------
__global__ void prep_bcat(const float* __restrict__ x,
                          const float* __restrict__ Wa1, const float* __restrict__ ba1,
                          const float* __restrict__ Wg1, const float* __restrict__ bg1) {
    __shared__ float xs[DIN];
    int c = threadIdx.x;                    // 256
    for (int k = c; k < DIN; k += 256) xs[k] = x[k];
    __syncthreads();
    const float* W = (c < MW) ? Wa1 : Wg1;
    int cc = c & (MW-1);
    float s = (c < MW) ? ba1[cc] : bg1[cc];
    for (int k = 0; k < DIN; k++) s += xs[k] * W[k*MW + cc];
    g_bcat[c] = s;
}

__global__ void prep_wcat(const float* __restrict__ Wa1, const float* __restrict__ Wg1) {
    int idx = blockIdx.x*256 + threadIdx.x;   // DH*256
    int k = idx >> 8, c = idx & 255;
    float v = (c < MW) ? Wa1[(DIN + k)*MW + c] : Wg1[(DIN + k)*MW + (c - MW)];
    g_Wcat[idx] = rnatf(v);
}

__global__ void prep_w2(const float* __restrict__ Wa2, const float* __restrict__ ba2,
                        const float* __restrict__ Wg2, const float* __restrict__ bg2) {
    int idx = blockIdx.x*256 + threadIdx.x;   // 256*DOUT
    int k = idx >> 9, n = idx & 511;
    float v = (k < MW) ? Wa2[k*DOUT + n] : -Wg2[(k - MW)*DOUT + n];
    g_W2cat[idx] = rnatf(v);
    if (idx < DOUT) g_b2[idx] = ba2[idx] - bg2[idx];
    if (idx < 18) g_cnt[idx] = 0;
}

__global__ void roundcopy_k(const float* __restrict__ s, float* __restrict__ d) {
    size_t i = (size_t)blockIdx.x*256 + threadIdx.x;
    float4 v = ((const float4*)s)[i];
    v.x = rnatf(v.x); v.y = rnatf(v.y); v.z = rnatf(v.z); v.w = rnatf(v.w);
    ((float4*)d)[i] = v;
}

__global__ void counts_k(const int* __restrict__ pos) {
    __shared__ int s[18];
    int tid = threadIdx.x;                    // 256, grid 64
    if (tid < 18) s[tid] = 0;
    __syncthreads();
    int i = blockIdx.x*256 + tid;
    int p = pos[i], f = i >> 11;
    if (p > 0)      { atomicAdd(&s[0], 1); atomicAdd(&s[2+f], 1); }
    else if (p < 0) { atomicAdd(&s[1], 1); atomicAdd(&s[10+f], 1); }
    __syncthreads();
    if (tid < 18 && s[tid]) atomicAdd(&g_cnt[tid], s[tid]);
}

// ---------------- tf32 mma.sync GEMM, double-buffered ----------------
// C[M,N] = A[M,K] @ B[K,N] + bias[N].  128x128 tile, BK=32, 8 warps 64x32.
// A: LDG->reg prefetch->STS(transposed).  B: cp.async into next stage.
// Inputs must be pre-rounded to tf32.
// MODE 0: plain. MODE 1: relu, store rounded. MODE 2: C exact + C2 rounded.
#define TILE_F 4352                 // 32*136 floats per operand per stage
#define GEMM_SMEM (4*TILE_F*4)      // 2 stages * (A+B) = 69632 bytes

template <int MODE>
__global__ __launch_bounds__(256, 2) void tgemm2(const float* __restrict__ A,
                                                 const float* __restrict__ B,
                                                 const float* __restrict__ bias,
                                                 float* __restrict__ C,
                                                 float* __restrict__ C2,
                                                 int M, int N, int K) {
    extern __shared__ float smem[];
    // layout: stage0 A | stage0 B | stage1 A | stage1 B
    int tid = threadIdx.x;
    int warp = tid >> 5, lane = tid & 31;
    int go = lane >> 2, tig = lane & 3;
    int wm = warp >> 2, wn = warp & 3;
    int by = blockIdx.y, bx = blockIdx.x;
    const float* Ab = A + (size_t)(by * 128) * K;
    const float* Bb = B + (size_t)bx * 128;

    int am = tid & 127;                       // A row
    int kh = (tid >> 7) * 16;                 // k half
    int bk = tid >> 3;                        // B k row 0..31
    int bn = (tid & 7) * 16;                  // B byte offset within 128B chunk

    float acc[4][4][4];
#pragma unroll
    for (int mt = 0; mt < 4; mt++)
#pragma unroll
        for (int nt = 0; nt < 4; nt++)
#pragma unroll
            for (int q = 0; q < 4; q++) acc[mt][nt][q] = 0.f;

    int T = K >> 5;
    float4 ra[4];

    // ---- prologue: tile 0 ----
    {
        const float* ap = Ab + (size_t)am * K + kh;
#pragma unroll
        for (int j = 0; j < 4; j++) ra[j] = *(const float4*)(ap + 4*j);
        uint32_t sB = s2u(smem + TILE_F) + bk*544 + bn;
        const float* bp = Bb + (size_t)bk * N + (tid & 7)*4;
#pragma unroll
        for (int j = 0; j < 4; j++)
            asm volatile("cp.async.cg.shared.global [%0], [%1], 16;"
                         :: "r"(sB + 128*j), "l"(bp + 32*j));
        asm volatile("cp.async.commit_group;");
        float* As = smem;
#pragma unroll
        for (int j = 0; j < 4; j++) {
            As[(kh+4*j+0)*136 + am] = ra[j].x;
            As[(kh+4*j+1)*136 + am] = ra[j].y;
            As[(kh+4*j+2)*136 + am] = ra[j].z;
            As[(kh+4*j+3)*136 + am] = ra[j].w;
        }
        asm volatile("cp.async.wait_group 0;");
        __syncthreads();
    }

    for (int t = 0; t < T; t++) {
        int cur = t & 1;
        float* As = smem + (cur ? 2*TILE_F : 0);
        float* Bs = As + TILE_F;
        bool more = (t + 1 < T);
        if (more) {
            int k0 = (t+1) * 32;
            const float* ap = Ab + (size_t)am * K + k0 + kh;
#pragma unroll
            for (int j = 0; j < 4; j++) ra[j] = *(const float4*)(ap + 4*j);
            float* Bn = smem + ((cur ^ 1) ? 2*TILE_F : 0) + TILE_F;
            uint32_t sB = s2u(Bn) + bk*544 + bn;
            const float* bp = Bb + (size_t)(k0 + bk) * N + (tid & 7)*4;
#pragma unroll
            for (int j = 0; j < 4; j++)
                asm volatile("cp.async.cg.shared.global [%0], [%1], 16;"
                             :: "r"(sB + 128*j), "l"(bp + 32*j));
            asm volatile("cp.async.commit_group;");
        }
        // ---- math on current stage ----
#pragma unroll
        for (int kk = 0; kk < 32; kk += 8) {
            uint32_t a[4][4], b[4][2];
#pragma unroll
            for (int mt = 0; mt < 4; mt++) {
                int ar = wm*64 + mt*16 + go;
                a[mt][0] = __float_as_uint(As[(kk + tig)*136 + ar]);
                a[mt][1] = __float_as_uint(As[(kk + tig)*136 + ar + 8]);
                a[mt][2] = __float_as_uint(As[(kk + tig + 4)*136 + ar]);
                a[mt][3] = __float_as_uint(As[(kk + tig + 4)*136 + ar + 8]);
            }
#pragma unroll
            for (int nt = 0; nt < 4; nt++) {
                int bc = wn*32 + nt*8 + go;
                b[nt][0] = __float_as_uint(Bs[(kk + tig)*136 + bc]);
                b[nt][1] = __float_as_uint(Bs[(kk + tig + 4)*136 + bc]);
            }
#pragma unroll
            for (int mt = 0; mt < 4; mt++)
#pragma unroll
                for (int nt = 0; nt < 4; nt++)
                    mma8(acc[mt][nt], a[mt], b[nt]);
        }
        if (more) {
            float* An = smem + ((cur ^ 1) ? 2*TILE_F : 0);
#pragma unroll
            for (int j = 0; j < 4; j++) {
                An[(kh+4*j+0)*136 + am] = ra[j].x;
                An[(kh+4*j+1)*136 + am] = ra[j].y;
                An[(kh+4*j+2)*136 + am] = ra[j].z;
                An[(kh+4*j+3)*136 + am] = ra[j].w;
            }
            asm volatile("cp.async.wait_group 0;");
        }
        __syncthreads();
    }

    // ---- epilogue ----
#pragma unroll
    for (int mt = 0; mt < 4; mt++) {
        int r0 = by*128 + wm*64 + mt*16 + go;
#pragma unroll
        for (int nt = 0; nt < 4; nt++) {
            int c = bx*128 + wn*32 + nt*8 + tig*2;
            float b0v = bias[c], b1v = bias[c+1];
            float v0 = acc[mt][nt][0] + b0v;
            float v1 = acc[mt][nt][1] + b1v;
            float v2 = acc[mt][nt][2] + b0v;
            float v3 = acc[mt][nt][3] + b1v;
            if (MODE == 1) {
                v0 = fmaxf(v0, 0.f); v1 = fmaxf(v1, 0.f);
                v2 = fmaxf(v2, 0.f); v3 = fmaxf(v3, 0.f);
                *(float2*)&C[(size_t)r0 * N + c]       = make_float2(rnatf(v0), rnatf(v1));
                *(float2*)&C[(size_t)(r0 + 8) * N + c] = make_float2(rnatf(v2), rnatf(v3));
            } else if (MODE == 2) {
                *(float2*)&C[(size_t)r0 * N + c]        = make_float2(v0, v1);
                *(float2*)&C[(size_t)(r0 + 8) * N + c]  = make_float2(v2, v3);
                *(float2*)&C2[(size_t)r0 * N + c]       = make_float2(rnatf(v0), rnatf(v1));
                *(float2*)&C2[(size_t)(r0 + 8) * N + c] = make_float2(rnatf(v2), rnatf(v3));
            } else {
                *(float2*)&C[(size_t)r0 * N + c]       = make_float2(v0, v1);
                *(float2*)&C[(size_t)(r0 + 8) * N + c] = make_float2(v2, v3);
            }
        }
    }
}

// ---------------- tension = mean(output^2, axis=-1) ----------------
__global__ void tension_k() {
    int i = blockIdx.x;
    int tid = threadIdx.x;                    // 128
    const float4* row = (const float4*)(g_out + (size_t)i * DOUT);
    float4 v = row[tid];
    float s = v.x*v.x + v.y*v.y + v.z*v.z + v.w*v.w;
#pragma unroll
    for (int o = 16; o > 0; o >>= 1) s += __shfl_xor_sync(0xffffffffu, s, o);
    __shared__ float ws[4];
    if ((tid & 31) == 0) ws[tid >> 5] = s;
    __syncthreads();
    if (tid == 0) g_tension[i] = (ws[0]+ws[1]+ws[2]+ws[3]) * (1.0f/DOUT);
}

// ---------------- GRU gates + wealth mod + clip ----------------
__global__ void gates_k(const float* __restrict__ h,
                        const float* __restrict__ Wih_t,   // W_ih row 512
                        const float* __restrict__ wealth) {
    int j = blockIdx.x*256 + threadIdx.x;     // 0..1023
    int i = blockIdx.y;
    size_t b = (size_t)i * H3;
    float t = g_tension[i];
    float gir = g_gi[b + j]        + t * Wih_t[j];
    float giz = g_gi[b + DH + j]   + t * Wih_t[DH + j];
    float gin = g_gi[b + 2*DH + j] + t * Wih_t[2*DH + j];
    float ghr = g_gh[b + j];
    float ghz = g_gh[b + DH + j];
    float ghn = g_gh[b + 2*DH + j];
    float r = 1.f / (1.f + expf(-(gir + ghr)));
    float z = 1.f / (1.f + expf(-(giz + ghz)));
    float n = tanhf(gin + r * ghn);
    float hv = h[(size_t)i*DH + j];
    float nh = (1.f - z) * n + z * hv;
    float w = fminf(fmaxf(wealth[i], 0.1f), 2.0f);
    nh = nh * (0.9f + 0.1f * w);
    nh = fminf(fmaxf(nh, -10.f), 10.f);
    g_h1[(size_t)i*DH + j] = nh;
}

// ---------------- per-column sums ----------------
__global__ void sums1_k(const int* __restrict__ pos) {
    int chunk = blockIdx.x;                   // 64
    int col = blockIdx.y*256 + threadIdx.x;
    float sa = 0.f, sp = 0.f, sn = 0.f;
    int base = chunk * 256;
    for (int r = 0; r < 256; r++) {
        int i = base + r;
        float v = g_h1[(size_t)i*DH + col];
        int p = pos[i];
        sa += v;
        if (p > 0) sp += v;
        else if (p < 0) sn += v;
    }
    g_part_all[chunk*DH + col] = sa;
    g_part_pos[chunk*DH + col] = sp;
    g_part_neg[chunk*DH + col] = sn;
}

__global__ void sums2_k() {
    int col = blockIdx.x*256 + threadIdx.x;
    int cp = g_cnt[0], cn = g_cnt[1];
    bool ap = cp >= 2, an = cn >= 2;
    float psum = 0.f, nsum = 0.f;
    for (int ch = 0; ch < 64; ch++) {
        psum += g_part_pos[ch*DH + col];
        nsum += g_part_neg[ch*DH + col];
    }
    float pm = psum / (float)(cp > 1 ? cp : 1);
    float nm = nsum / (float)(cn > 1 ? cn : 1);
    g_pm[col] = pm; g_nm[col] = nm;
    float gop = 0.f;
    for (int f = 0; f < 8; f++) {
        float a = 0.f, p = 0.f, nn = 0.f;
        for (int c = 0; c < 8; c++) {
            int ch = f*8 + c;
            a  += g_part_all[ch*DH + col];
            p  += g_part_pos[ch*DH + col];
            nn += g_part_neg[ch*DH + col];
        }
        float s = a;
        if (ap) s += -0.1f * p  + 0.1f * (float)g_cnt[2+f]  * pm;
        if (an) s += -0.1f * nn + 0.1f * (float)g_cnt[10+f] * nm;
        float fm = s * (1.f/2048.f);
        g_fmean[f*DH + col] = fm;
        gop += fm;
    }
    g_gop[col] = gop * 0.125f;
}

__global__ void blend_k(const int* __restrict__ pos, const int* __restrict__ step_p,
                        float* __restrict__ outh) {
    int j = blockIdx.x*256 + threadIdx.x;
    int i = blockIdx.y;
    float h2 = g_h1[(size_t)i*DH + j];
    int p = pos[i];
    if (p > 0 && g_cnt[0] >= 2)      h2 = 0.9f*h2 + 0.1f*g_pm[j];
    else if (p < 0 && g_cnt[1] >= 2) h2 = 0.9f*h2 + 0.1f*g_nm[j];
    int f = i >> 11;
    float h3 = 0.85f*h2 + 0.15f*g_fmean[f*DH + j];
    if ((i & 2047) < 512 && step_p[0] > 5) h3 = 0.85f*h3 + 0.15f*g_gop[j];
    outh[(size_t)i*DH + j] = h3;
}

__global__ void smax_k(float* __restrict__ out, int avg_off) {
    int tid = threadIdx.x;                    // 1024
    float m = -3.4e38f;
    for (int i = tid; i < NC; i += 1024) m = fmaxf(m, g_tension[i]);
#pragma unroll
    for (int o = 16; o > 0; o >>= 1) m = fmaxf(m, __shfl_xor_sync(0xffffffffu, m, o));
    __shared__ float red[32];
    if ((tid & 31) == 0) red[tid >> 5] = m;
    __syncthreads();
    if (tid < 32) {
        float v = red[tid];
#pragma unroll
        for (int o = 16; o > 0; o >>= 1) v = fmaxf(v, __shfl_xor_sync(0xffffffffu, v, o));
        if (tid == 0) red[0] = v;
    }
    __syncthreads();
    float mm = red[0];
    __syncthreads();
    float se = 0.f, st = 0.f;
    for (int i = tid; i < NC; i += 1024) {
        float t = g_tension[i];
        st += t;
        float e = expf(t - mm);
        se += e;
        g_wts[i] = e;
    }
#pragma unroll
    for (int o = 16; o > 0; o >>= 1) {
        se += __shfl_xor_sync(0xffffffffu, se, o);
        st += __shfl_xor_sync(0xffffffffu, st, o);
    }
    __shared__ float r2[32], r3[32];
    if ((tid & 31) == 0) { r2[tid >> 5] = se; r3[tid >> 5] = st; }
    __syncthreads();
    if (tid == 0) {
        float a = 0.f, b = 0.f;
        for (int w = 0; w < 32; w++) { a += r2[w]; b += r3[w]; }
        g_soft[0] = mm; g_soft[1] = a;
        out[avg_off] = b * (1.f/NC);
    }
}

__global__ void wsum_k() {
    int j = threadIdx.x;                      // 512
    int b = blockIdx.x;                       // 64
    float s = 0.f;
    int base = b * 256;
    for (int r = 0; r < 256; r++) {
        int i = base + r;
        s += g_wts[i] * g_out[(size_t)i*DOUT + j];
    }
    g_partial[b*DOUT + j] = s;
}

__global__ void pred_k(const float* __restrict__ Wo, const float* __restrict__ bo,
                       float* __restrict__ out) {
    __shared__ float comb[DOUT];
    int j = threadIdx.x;                      // 512
    float s = 0.f;
    for (int b = 0; b < 64; b++) s += g_partial[b*DOUT + j];
    comb[j] = s / g_soft[1];
    __syncthreads();
    float p = bo[j];
    for (int k = 0; k < DOUT; k++) p += comb[k] * Wo[k*DOUT + j];
    out[j] = p;
}

// ---------------- launch ----------------
extern "C" void kernel_launch(void* const* d_in, const int* in_sizes, int n_in,
                              void* d_out, int out_size) {
    const float* x       = (const float*)d_in[0];
    const float* hiddens = (const float*)d_in[1];
    const float* wealth  = (const float*)d_in[2];
    const float* Wa1     = (const float*)d_in[3];
    const float* ba1     = (const float*)d_in[4];
    const float* Wa2     = (const float*)d_in[5];
    const float* ba2     = (const float*)d_in[6];
    const float* Wg1     = (const float*)d_in[7];
    const float* bg1     = (const float*)d_in[8];
    const float* Wg2     = (const float*)d_in[9];
    const float* bg2     = (const float*)d_in[10];
    const float* W_ih    = (const float*)d_in[11];
    const float* W_hh    = (const float*)d_in[12];
    const float* b_ih    = (const float*)d_in[13];
    const float* b_hh    = (const float*)d_in[14];
    const float* Wo      = (const float*)d_in[15];
    const float* bo      = (const float*)d_in[16];
    const int*   pos     = (const int*)d_in[17];
    const int*   step    = (const int*)d_in[18];
    float* out = (float*)d_out;

    size_t newh_off = (size_t)out_size - (size_t)NC * DH;
    int avg_off = (int)(newh_off - 1);

    float *dWcat, *dbcat, *dW2, *db2, *dWihR, *dWhhR, *dHr, *dA1, *dOut, *dOutr, *dGi, *dGh;
    cudaGetSymbolAddress((void**)&dWcat, g_Wcat);
    cudaGetSymbolAddress((void**)&dbcat, g_bcat);
    cudaGetSymbolAddress((void**)&dW2,   g_W2cat);
    cudaGetSymbolAddress((void**)&db2,   g_b2);
    cudaGetSymbolAddress((void**)&dWihR, g_WihR);
    cudaGetSymbolAddress((void**)&dWhhR, g_WhhR);
    cudaGetSymbolAddress((void**)&dHr,   g_hr);
    cudaGetSymbolAddress((void**)&dA1,   g_A1);
    cudaGetSymbolAddress((void**)&dOut,  g_out);
    cudaGetSymbolAddress((void**)&dOutr, g_outr);
    cudaGetSymbolAddress((void**)&dGi,   g_gi);
    cudaGetSymbolAddress((void**)&dGh,   g_gh);

    cudaFuncSetAttribute(tgemm2<0>, cudaFuncAttributeMaxDynamicSharedMemorySize, GEMM_SMEM);
    cudaFuncSetAttribute(tgemm2<1>, cudaFuncAttributeMaxDynamicSharedMemorySize, GEMM_SMEM);
    cudaFuncSetAttribute(tgemm2<2>, cudaFuncAttributeMaxDynamicSharedMemorySize, GEMM_SMEM);

    // prep (round everything to tf32 once)
    prep_bcat<<<1, 256>>>(x, Wa1, ba1, Wg1, bg1);
    prep_wcat<<<(DH*256)/256, 256>>>(Wa1, Wg1);
    prep_w2<<<(256*DOUT)/256, 256>>>(Wa2, ba2, Wg2, bg2);
    counts_k<<<64, 256>>>(pos);
    roundcopy_k<<<(DOUT*H3/4)/256, 256>>>(W_ih, dWihR);      // first 512 rows of W_ih
    roundcopy_k<<<(DH*H3/4)/256, 256>>>(W_hh, dWhhR);
    roundcopy_k<<<((size_t)NC*DH/4)/256, 256>>>(hiddens, dHr);

    // G1: A1 = rna(relu(hr @ Wcat + bcat))   [16384, 256]
    tgemm2<1><<<dim3(2, NC/128), 256, GEMM_SMEM>>>(dHr, dWcat, dbcat, dA1, nullptr, NC, 256, DH);
    // G2: out = A1 @ W2cat + b2   [16384, 512]  exact + rounded copy
    tgemm2<2><<<dim3(DOUT/128, NC/128), 256, GEMM_SMEM>>>(dA1, dW2, db2, dOut, dOutr, NC, DOUT, 256);
    // tension
    tension_k<<<NC, 128>>>();
    // G3: gi = outr @ WihR + b_ih   [16384, 3072]
    tgemm2<0><<<dim3(H3/128, NC/128), 256, GEMM_SMEM>>>(dOutr, dWihR, b_ih, dGi, nullptr, NC, H3, DOUT);
    // G4: gh = hr @ WhhR + b_hh   [16384, 3072]
    tgemm2<0><<<dim3(H3/128, NC/128), 256, GEMM_SMEM>>>(dHr, dWhhR, b_hh, dGh, nullptr, NC, H3, DH);
    // gates
    gates_k<<<dim3(DH/256, NC), 256>>>(hiddens, W_ih + (size_t)DIN*H3, wealth);
    // sync reductions
    sums1_k<<<dim3(64, DH/256), 256>>>(pos);
    sums2_k<<<DH/256, 256>>>();
    // final blend -> new_h
    blend_k<<<dim3(DH/256, NC), 256>>>(pos, step, out + newh_off);
    // softmax + weighted combine + pred
    smax_k<<<1, 1024>>>(out, avg_off);
    wsum_k<<<64, DOUT>>>();
    pred_k<<<1, DOUT>>>(Wo, bo, out);
}

// round 9
// speedup vs baseline: 3.4912x; 1.5519x over previous
#include <cuda_runtime.h>
#include <cuda_fp16.h>
#include <math.h>
#include <stdint.h>

#define NC    16384
#define DIN   512
#define DH    1024
#define DOUT  512
#define MW    128
#define H3    (3*DH)

// ---------------- scratch (__device__ globals) ----------------
__device__ __half g_WcatH[DH*256];           // [K=1024][N=256] fp16
__device__ float  g_bcat[256];
__device__ __half g_W2H[256*DOUT];           // [K=256][N=512] fp16 (Wa2 ; -Wg2)
__device__ float  g_b2[DOUT];
__device__ __half g_WihH[(size_t)DOUT*H3];   // fp16 W_ih[0:512]
__device__ __half g_WhhH[(size_t)DH*H3];     // fp16 W_hh
__device__ __half g_hH[(size_t)NC*DH];       // fp16 hiddens
__device__ __half g_A1H[(size_t)NC*256];     // fp16 relu layer-1
__device__ float  g_out[(size_t)NC*DOUT];    // exact output = a - g
__device__ __half g_outH[(size_t)NC*DOUT];   // fp16 copy for G3
__device__ float  g_tension[NC];
__device__ float  g_gi[(size_t)NC*H3];
__device__ float  g_gh[(size_t)NC*H3];
__device__ float  g_h1[(size_t)NC*DH];
__device__ float  g_part_all[64*DH];
__device__ float  g_part_pos[64*DH];
__device__ float  g_part_neg[64*DH];
__device__ float  g_fmean[8*DH];
__device__ float  g_gop[DH];
__device__ float  g_pm[DH];
__device__ float  g_nm[DH];
__device__ int    g_cnt[18];
__device__ float  g_soft[2];
__device__ float  g_wts[NC];
__device__ float  g_partial[64*DOUT];

// ---------------- helpers ----------------
__device__ __forceinline__ void mma16(float* c, const uint32_t* a, const uint32_t* b) {
    asm volatile("mma.sync.aligned.m16n8k16.row.col.f32.f16.f16.f32 "
        "{%0,%1,%2,%3}, {%4,%5,%6,%7}, {%8,%9}, {%0,%1,%2,%3};"
        : "+f"(c[0]), "+f"(c[1]), "+f"(c[2]), "+f"(c[3])
        : "r"(a[0]), "r"(a[1]), "r"(a[2]), "r"(a[3]), "r"(b[0]), "r"(b[1]));
}

// ---------------- prep kernels ----------------
__global__ void prep_bcat(const float* __restrict__ x,
                          const float* __restrict__ Wa1, const float* __restrict__ ba1,
                          const float* __restrict__ Wg1, const float* __restrict__ bg1) {
    __shared__ float xs[DIN];
    int c = threadIdx.x;                    // 256
    for (int k = c; k < DIN; k += 256) xs[k] = x[k];
    __syncthreads();
    const float* W = (c < MW) ? Wa1 : Wg1;
    int cc = c & (MW-1);
    float s = (c < MW) ? ba1[cc] : bg1[cc];
    for (int k = 0; k < DIN; k++) s += xs[k] * W[k*MW + cc];
    g_bcat[c] = s;
}

__global__ void prep_wcat(const float* __restrict__ Wa1, const float* __restrict__ Wg1) {
    int idx = blockIdx.x*256 + threadIdx.x;   // DH*256
    int k = idx >> 8, c = idx & 255;
    float v = (c < MW) ? Wa1[(DIN + k)*MW + c] : Wg1[(DIN + k)*MW + (c - MW)];
    g_WcatH[idx] = __float2half_rn(v);
}

__global__ void prep_w2(const float* __restrict__ Wa2, const float* __restrict__ ba2,
                        const float* __restrict__ Wg2, const float* __restrict__ bg2) {
    int idx = blockIdx.x*256 + threadIdx.x;   // 256*DOUT
    int k = idx >> 9, n = idx & 511;
    float v = (k < MW) ? Wa2[k*DOUT + n] : -Wg2[(k - MW)*DOUT + n];
    g_W2H[idx] = __float2half_rn(v);
    if (idx < DOUT) g_b2[idx] = ba2[idx] - bg2[idx];
    if (idx < 18) g_cnt[idx] = 0;
}

__global__ void halfcopy_k(const float* __restrict__ s, __half* __restrict__ d) {
    size_t i = (size_t)blockIdx.x*256 + threadIdx.x;
    float4 v = ((const float4*)s)[i];
    __half2 lo = __floats2half2_rn(v.x, v.y);
    __half2 hi = __floats2half2_rn(v.z, v.w);
    ((__half2*)d)[2*i]   = lo;
    ((__half2*)d)[2*i+1] = hi;
}

__global__ void counts_k(const int* __restrict__ pos) {
    __shared__ int s[18];
    int tid = threadIdx.x;                    // 256, grid 64
    if (tid < 18) s[tid] = 0;
    __syncthreads();
    int i = blockIdx.x*256 + tid;
    int p = pos[i], f = i >> 11;
    if (p > 0)      { atomicAdd(&s[0], 1); atomicAdd(&s[2+f], 1); }
    else if (p < 0) { atomicAdd(&s[1], 1); atomicAdd(&s[10+f], 1); }
    __syncthreads();
    if (tid < 18 && s[tid]) atomicAdd(&g_cnt[tid], s[tid]);
}

// ---------------- fp16 mma.sync GEMM, double-buffered ----------------
// C[M,N] = A[M,K] @ B[K,N] + bias[N].  A,B fp16; acc fp32.
// 128x128 tile, BK=32, 8 warps 64x32, m16n8k16.
// smem: k-pair-interleaved half2 tiles [k/2][dim], row stride 136 half2.
// MODE 0: C fp32. MODE 1: relu -> Ch fp16. MODE 2: C fp32 + Ch fp16.
#define HTILE 2176                  // 16*136 uint32 per operand per stage
#define HGEMM_SMEM (4*HTILE*4)      // 2 stages * (A+B) = 34816 bytes

template <int MODE>
__global__ __launch_bounds__(256, 2) void hgemm(const __half* __restrict__ A,
                                                const __half* __restrict__ B,
                                                const float* __restrict__ bias,
                                                float* __restrict__ C,
                                                __half* __restrict__ Ch,
                                                int M, int N, int K) {
    extern __shared__ uint32_t sm[];
    int tid = threadIdx.x;
    int warp = tid >> 5, lane = tid & 31;
    int go = lane >> 2, tig = lane & 3;
    int wm = warp >> 2, wn = warp & 3;
    const __half* Ab = A + (size_t)(blockIdx.y * 128) * K;
    const __half* Bb = B + (size_t)blockIdx.x * 128;

    int am = tid & 127;               // A row
    int kh = (tid >> 7) * 16;         // A k offset (0 or 16)
    int br = tid >> 4;                // B pair-row 0..15
    int bc = (tid & 15) * 8;          // B col base

    float acc[4][4][4];
#pragma unroll
    for (int mt = 0; mt < 4; mt++)
#pragma unroll
        for (int nt = 0; nt < 4; nt++)
#pragma unroll
            for (int q = 0; q < 4; q++) acc[mt][nt][q] = 0.f;

    int T = K >> 5;
    uint4 raA0, raA1, rb0, rb1;

#define LDG_TILE(t) do { \
        const __half* ap = Ab + (size_t)am * K + (t)*32 + kh; \
        raA0 = *(const uint4*)ap; raA1 = *(const uint4*)(ap + 8); \
        const __half* bp = Bb + (size_t)((t)*32 + 2*br) * N + bc; \
        rb0 = *(const uint4*)bp; rb1 = *(const uint4*)(bp + N); \
    } while (0)

#define STS_TILE(stage) do { \
        uint32_t* As = sm + (stage)*2*HTILE; \
        uint32_t* Bs = As + HTILE; \
        uint32_t w0[8] = {raA0.x, raA0.y, raA0.z, raA0.w, raA1.x, raA1.y, raA1.z, raA1.w}; \
        int kp = kh >> 1; \
        _Pragma("unroll") \
        for (int j = 0; j < 8; j++) As[(kp + j)*136 + am] = w0[j]; \
        uint32_t q0 = __byte_perm(rb0.x, rb1.x, 0x5410), q1 = __byte_perm(rb0.x, rb1.x, 0x7632); \
        uint32_t q2 = __byte_perm(rb0.y, rb1.y, 0x5410), q3 = __byte_perm(rb0.y, rb1.y, 0x7632); \
        uint32_t q4 = __byte_perm(rb0.z, rb1.z, 0x5410), q5 = __byte_perm(rb0.z, rb1.z, 0x7632); \
        uint32_t q6 = __byte_perm(rb0.w, rb1.w, 0x5410), q7 = __byte_perm(rb0.w, rb1.w, 0x7632); \
        *(uint4*)&Bs[br*136 + bc]     = make_uint4(q0, q1, q2, q3); \
        *(uint4*)&Bs[br*136 + bc + 4] = make_uint4(q4, q5, q6, q7); \
    } while (0)

    // prologue
    LDG_TILE(0);
    STS_TILE(0);
    __syncthreads();

    for (int t = 0; t < T; t++) {
        bool more = (t + 1 < T);
        if (more) LDG_TILE(t+1);
        // math on stage t&1
        uint32_t* As = sm + (t & 1)*2*HTILE;
        uint32_t* Bs = As + HTILE;
#pragma unroll
        for (int ks = 0; ks < 2; ks++) {
            int kb = ks * 8;
            uint32_t a[4][4], b[4][2];
#pragma unroll
            for (int mt = 0; mt < 4; mt++) {
                int ar = wm*64 + mt*16 + go;
                a[mt][0] = As[(kb + tig)*136 + ar];
                a[mt][1] = As[(kb + tig)*136 + ar + 8];
                a[mt][2] = As[(kb + tig + 4)*136 + ar];
                a[mt][3] = As[(kb + tig + 4)*136 + ar + 8];
            }
#pragma unroll
            for (int nt = 0; nt < 4; nt++) {
                int bq = wn*32 + nt*8 + go;
                b[nt][0] = Bs[(kb + tig)*136 + bq];
                b[nt][1] = Bs[(kb + tig + 4)*136 + bq];
            }
#pragma unroll
            for (int mt = 0; mt < 4; mt++)
#pragma unroll
                for (int nt = 0; nt < 4; nt++)
                    mma16(acc[mt][nt], a[mt], b[nt]);
        }
        if (more) STS_TILE((t+1) & 1);
        __syncthreads();
    }

    // epilogue
#pragma unroll
    for (int mt = 0; mt < 4; mt++) {
        int r0 = blockIdx.y*128 + wm*64 + mt*16 + go;
#pragma unroll
        for (int nt = 0; nt < 4; nt++) {
            int c = blockIdx.x*128 + wn*32 + nt*8 + tig*2;
            float b0v = bias[c], b1v = bias[c+1];
            float v0 = acc[mt][nt][0] + b0v;
            float v1 = acc[mt][nt][1] + b1v;
            float v2 = acc[mt][nt][2] + b0v;
            float v3 = acc[mt][nt][3] + b1v;
            if (MODE == 1) {
                v0 = fmaxf(v0, 0.f); v1 = fmaxf(v1, 0.f);
                v2 = fmaxf(v2, 0.f); v3 = fmaxf(v3, 0.f);
                *(__half2*)&Ch[(size_t)r0 * N + c]       = __floats2half2_rn(v0, v1);
                *(__half2*)&Ch[(size_t)(r0 + 8) * N + c] = __floats2half2_rn(v2, v3);
            } else if (MODE == 2) {
                *(float2*)&C[(size_t)r0 * N + c]         = make_float2(v0, v1);
                *(float2*)&C[(size_t)(r0 + 8) * N + c]   = make_float2(v2, v3);
                *(__half2*)&Ch[(size_t)r0 * N + c]       = __floats2half2_rn(v0, v1);
                *(__half2*)&Ch[(size_t)(r0 + 8) * N + c] = __floats2half2_rn(v2, v3);
            } else {
                *(float2*)&C[(size_t)r0 * N + c]       = make_float2(v0, v1);
                *(float2*)&C[(size_t)(r0 + 8) * N + c] = make_float2(v2, v3);
            }
        }
    }
#undef LDG_TILE
#undef STS_TILE
}

// ---------------- tension = mean(output^2, axis=-1) ----------------
__global__ void tension_k() {
    int i = blockIdx.x;
    int tid = threadIdx.x;                    // 128
    const float4* row = (const float4*)(g_out + (size_t)i * DOUT);
    float4 v = row[tid];
    float s = v.x*v.x + v.y*v.y + v.z*v.z + v.w*v.w;
#pragma unroll
    for (int o = 16; o > 0; o >>= 1) s += __shfl_xor_sync(0xffffffffu, s, o);
    __shared__ float ws[4];
    if ((tid & 31) == 0) ws[tid >> 5] = s;
    __syncthreads();
    if (tid == 0) g_tension[i] = (ws[0]+ws[1]+ws[2]+ws[3]) * (1.0f/DOUT);
}

// ---------------- GRU gates + wealth mod + clip ----------------
__global__ void gates_k(const float* __restrict__ h,
                        const float* __restrict__ Wih_t,   // W_ih row 512
                        const float* __restrict__ wealth) {
    int j = blockIdx.x*256 + threadIdx.x;     // 0..1023
    int i = blockIdx.y;
    size_t b = (size_t)i * H3;
    float t = g_tension[i];
    float gir = g_gi[b + j]        + t * Wih_t[j];
    float giz = g_gi[b + DH + j]   + t * Wih_t[DH + j];
    float gin = g_gi[b + 2*DH + j] + t * Wih_t[2*DH + j];
    float ghr = g_gh[b + j];
    float ghz = g_gh[b + DH + j];
    float ghn = g_gh[b + 2*DH + j];
    float r = 1.f / (1.f + expf(-(gir + ghr)));
    float z = 1.f / (1.f + expf(-(giz + ghz)));
    float n = tanhf(gin + r * ghn);
    float hv = h[(size_t)i*DH + j];
    float nh = (1.f - z) * n + z * hv;
    float w = fminf(fmaxf(wealth[i], 0.1f), 2.0f);
    nh = nh * (0.9f + 0.1f * w);
    nh = fminf(fmaxf(nh, -10.f), 10.f);
    g_h1[(size_t)i*DH + j] = nh;
}

// ---------------- per-column sums ----------------
__global__ void sums1_k(const int* __restrict__ pos) {
    int chunk = blockIdx.x;                   // 64
    int col = blockIdx.y*256 + threadIdx.x;
    float sa = 0.f, sp = 0.f, sn = 0.f;
    int base = chunk * 256;
    for (int r = 0; r < 256; r++) {
        int i = base + r;
        float v = g_h1[(size_t)i*DH + col];
        int p = pos[i];
        sa += v;
        if (p > 0) sp += v;
        else if (p < 0) sn += v;
    }
    g_part_all[chunk*DH + col] = sa;
    g_part_pos[chunk*DH + col] = sp;
    g_part_neg[chunk*DH + col] = sn;
}

__global__ void sums2_k() {
    int col = blockIdx.x*256 + threadIdx.x;
    int cp = g_cnt[0], cn = g_cnt[1];
    bool ap = cp >= 2, an = cn >= 2;
    float psum = 0.f, nsum = 0.f;
    for (int ch = 0; ch < 64; ch++) {
        psum += g_part_pos[ch*DH + col];
        nsum += g_part_neg[ch*DH + col];
    }
    float pm = psum / (float)(cp > 1 ? cp : 1);
    float nm = nsum / (float)(cn > 1 ? cn : 1);
    g_pm[col] = pm; g_nm[col] = nm;
    float gop = 0.f;
    for (int f = 0; f < 8; f++) {
        float a = 0.f, p = 0.f, nn = 0.f;
        for (int c = 0; c < 8; c++) {
            int ch = f*8 + c;
            a  += g_part_all[ch*DH + col];
            p  += g_part_pos[ch*DH + col];
            nn += g_part_neg[ch*DH + col];
        }
        float s = a;
        if (ap) s += -0.1f * p  + 0.1f * (float)g_cnt[2+f]  * pm;
        if (an) s += -0.1f * nn + 0.1f * (float)g_cnt[10+f] * nm;
        float fm = s * (1.f/2048.f);
        g_fmean[f*DH + col] = fm;
        gop += fm;
    }
    g_gop[col] = gop * 0.125f;
}

__global__ void blend_k(const int* __restrict__ pos, const int* __restrict__ step_p,
                        float* __restrict__ outh) {
    int j = blockIdx.x*256 + threadIdx.x;
    int i = blockIdx.y;
    float h2 = g_h1[(size_t)i*DH + j];
    int p = pos[i];
    if (p > 0 && g_cnt[0] >= 2)      h2 = 0.9f*h2 + 0.1f*g_pm[j];
    else if (p < 0 && g_cnt[1] >= 2) h2 = 0.9f*h2 + 0.1f*g_nm[j];
    int f = i >> 11;
    float h3 = 0.85f*h2 + 0.15f*g_fmean[f*DH + j];
    if ((i & 2047) < 512 && step_p[0] > 5) h3 = 0.85f*h3 + 0.15f*g_gop[j];
    outh[(size_t)i*DH + j] = h3;
}

__global__ void smax_k(float* __restrict__ out, int avg_off) {
    int tid = threadIdx.x;                    // 1024
    float m = -3.4e38f;
    for (int i = tid; i < NC; i += 1024) m = fmaxf(m, g_tension[i]);
#pragma unroll
    for (int o = 16; o > 0; o >>= 1) m = fmaxf(m, __shfl_xor_sync(0xffffffffu, m, o));
    __shared__ float red[32];
    if ((tid & 31) == 0) red[tid >> 5] = m;
    __syncthreads();
    if (tid < 32) {
        float v = red[tid];
#pragma unroll
        for (int o = 16; o > 0; o >>= 1) v = fmaxf(v, __shfl_xor_sync(0xffffffffu, v, o));
        if (tid == 0) red[0] = v;
    }
    __syncthreads();
    float mm = red[0];
    __syncthreads();
    float se = 0.f, st = 0.f;
    for (int i = tid; i < NC; i += 1024) {
        float t = g_tension[i];
        st += t;
        float e = expf(t - mm);
        se += e;
        g_wts[i] = e;
    }
#pragma unroll
    for (int o = 16; o > 0; o >>= 1) {
        se += __shfl_xor_sync(0xffffffffu, se, o);
        st += __shfl_xor_sync(0xffffffffu, st, o);
    }
    __shared__ float r2[32], r3[32];
    if ((tid & 31) == 0) { r2[tid >> 5] = se; r3[tid >> 5] = st; }
    __syncthreads();
    if (tid == 0) {
        float a = 0.f, b = 0.f;
        for (int w = 0; w < 32; w++) { a += r2[w]; b += r3[w]; }
        g_soft[0] = mm; g_soft[1] = a;
        out[avg_off] = b * (1.f/NC);
    }
}

__global__ void wsum_k() {
    int j = threadIdx.x;                      // 512
    int b = blockIdx.x;                       // 64
    float s = 0.f;
    int base = b * 256;
    for (int r = 0; r < 256; r++) {
        int i = base + r;
        s += g_wts[i] * g_out[(size_t)i*DOUT + j];
    }
    g_partial[b*DOUT + j] = s;
}

__global__ void pred_k(const float* __restrict__ Wo, const float* __restrict__ bo,
                       float* __restrict__ out) {
    __shared__ float comb[DOUT];
    int j = threadIdx.x;                      // 512
    float s = 0.f;
    for (int b = 0; b < 64; b++) s += g_partial[b*DOUT + j];
    comb[j] = s / g_soft[1];
    __syncthreads();
    float p = bo[j];
    for (int k = 0; k < DOUT; k++) p += comb[k] * Wo[k*DOUT + j];
    out[j] = p;
}

// ---------------- launch ----------------
extern "C" void kernel_launch(void* const* d_in, const int* in_sizes, int n_in,
                              void* d_out, int out_size) {
    const float* x       = (const float*)d_in[0];
    const float* hiddens = (const float*)d_in[1];
    const float* wealth  = (const float*)d_in[2];
    const float* Wa1     = (const float*)d_in[3];
    const float* ba1     = (const float*)d_in[4];
    const float* Wa2     = (const float*)d_in[5];
    const float* ba2     = (const float*)d_in[6];
    const float* Wg1     = (const float*)d_in[7];
    const float* bg1     = (const float*)d_in[8];
    const float* Wg2     = (const float*)d_in[9];
    const float* bg2     = (const float*)d_in[10];
    const float* W_ih    = (const float*)d_in[11];
    const float* W_hh    = (const float*)d_in[12];
    const float* b_ih    = (const float*)d_in[13];
    const float* b_hh    = (const float*)d_in[14];
    const float* Wo      = (const float*)d_in[15];
    const float* bo      = (const float*)d_in[16];
    const int*   pos     = (const int*)d_in[17];
    const int*   step    = (const int*)d_in[18];
    float* out = (float*)d_out;

    size_t newh_off = (size_t)out_size - (size_t)NC * DH;
    int avg_off = (int)(newh_off - 1);

    float *dbcat, *db2, *dOut, *dGi, *dGh;
    __half *dWcatH, *dW2H, *dWihH, *dWhhH, *dHH, *dA1H, *dOutH;
    cudaGetSymbolAddress((void**)&dWcatH, g_WcatH);
    cudaGetSymbolAddress((void**)&dbcat,  g_bcat);
    cudaGetSymbolAddress((void**)&dW2H,   g_W2H);
    cudaGetSymbolAddress((void**)&db2,    g_b2);
    cudaGetSymbolAddress((void**)&dWihH,  g_WihH);
    cudaGetSymbolAddress((void**)&dWhhH,  g_WhhH);
    cudaGetSymbolAddress((void**)&dHH,    g_hH);
    cudaGetSymbolAddress((void**)&dA1H,   g_A1H);
    cudaGetSymbolAddress((void**)&dOut,   g_out);
    cudaGetSymbolAddress((void**)&dOutH,  g_outH);
    cudaGetSymbolAddress((void**)&dGi,    g_gi);
    cudaGetSymbolAddress((void**)&dGh,    g_gh);

    // prep (convert everything to fp16 once)
    prep_bcat<<<1, 256>>>(x, Wa1, ba1, Wg1, bg1);
    prep_wcat<<<(DH*256)/256, 256>>>(Wa1, Wg1);
    prep_w2<<<(256*DOUT)/256, 256>>>(Wa2, ba2, Wg2, bg2);
    counts_k<<<64, 256>>>(pos);
    halfcopy_k<<<(DOUT*H3/4)/256, 256>>>(W_ih, dWihH);       // first 512 rows of W_ih
    halfcopy_k<<<(DH*H3/4)/256, 256>>>(W_hh, dWhhH);
    halfcopy_k<<<(int)(((size_t)NC*DH/4)/256), 256>>>(hiddens, dHH);

    // G1: A1H = fp16(relu(hH @ WcatH + bcat))   [16384, 256]
    hgemm<1><<<dim3(2, NC/128), 256, HGEMM_SMEM>>>(dHH, dWcatH, dbcat, nullptr, dA1H, NC, 256, DH);
    // G2: out = A1H @ W2H + b2   [16384, 512]  fp32 exact + fp16 copy
    hgemm<2><<<dim3(DOUT/128, NC/128), 256, HGEMM_SMEM>>>(dA1H, dW2H, db2, dOut, dOutH, NC, DOUT, 256);
    // tension
    tension_k<<<NC, 128>>>();
    // G3: gi = outH @ WihH + b_ih   [16384, 3072]
    hgemm<0><<<dim3(H3/128, NC/128), 256, HGEMM_SMEM>>>(dOutH, dWihH, b_ih, dGi, nullptr, NC, H3, DOUT);
    // G4: gh = hH @ WhhH + b_hh   [16384, 3072]
    hgemm<0><<<dim3(H3/128, NC/128), 256, HGEMM_SMEM>>>(dHH, dWhhH, b_hh, dGh, nullptr, NC, H3, DH);
    // gates
    gates_k<<<dim3(DH/256, NC), 256>>>(hiddens, W_ih + (size_t)DIN*H3, wealth);
    // sync reductions
    sums1_k<<<dim3(64, DH/256), 256>>>(pos);
    sums2_k<<<DH/256, 256>>>();
    // final blend -> new_h
    blend_k<<<dim3(DH/256, NC), 256>>>(pos, step, out + newh_off);
    // softmax + weighted combine + pred
    smax_k<<<1, 1024>>>(out, avg_off);
    wsum_k<<<64, DOUT>>>();
    pred_k<<<1, DOUT>>>(Wo, bo, out);
}

// round 11
// speedup vs baseline: 3.4969x; 1.0016x over previous
#include <cuda_runtime.h>
#include <cuda_fp16.h>
#include <math.h>
#include <stdint.h>

#define NC    16384
#define DIN   512
#define DH    1024
#define DOUT  512
#define MW    128
#define H3    (3*DH)

// ---------------- scratch (__device__ globals) ----------------
__device__ __half g_WcatH[DH*256];           // [K=1024][N=256] fp16
__device__ float  g_bcat[256];
__device__ __half g_W2H[256*DOUT];           // [K=256][N=512] fp16 (Wa2 ; -Wg2)
__device__ float  g_b2[DOUT];
__device__ __half g_WihH[(size_t)DOUT*H3];   // fp16 W_ih[0:512]  (full 3072 cols)
__device__ __half g_WhhH[(size_t)DH*H3];     // fp16 W_hh         (full 3072 cols)
__device__ __half g_WrzH[(size_t)1536*2048]; // fp16 [Wih_rz ; Whh_rz]
__device__ float  g_brz[2048];               // b_ih+b_hh (r,z)
__device__ __half g_catH[(size_t)NC*1536];   // [outH | hH] fp16, row stride 1536
__device__ __half g_A1H[(size_t)NC*256];     // fp16 relu layer-1
__device__ float  g_out[(size_t)NC*DOUT];    // exact output = a - g
__device__ float  g_rz[(size_t)NC*2048];     // fused r,z pre-activations
__device__ float  g_gin[(size_t)NC*DH];      // gi_n
__device__ float  g_tension[NC];
__device__ float  g_h1[(size_t)NC*DH];
__device__ float  g_part_all[64*DH];
__device__ float  g_part_pos[64*DH];
__device__ float  g_part_neg[64*DH];
__device__ float  g_fmean[8*DH];
__device__ float  g_gop[DH];
__device__ float  g_pm[DH];
__device__ float  g_nm[DH];
__device__ int    g_cnt[18];
__device__ float  g_soft[2];
__device__ float  g_wts[NC];
__device__ float  g_partial[64*DOUT];

// ---------------- helpers ----------------
__device__ __forceinline__ void mma16(float* c, const uint32_t* a, const uint32_t* b) {
    asm volatile("mma.sync.aligned.m16n8k16.row.col.f32.f16.f16.f32 "
        "{%0,%1,%2,%3}, {%4,%5,%6,%7}, {%8,%9}, {%0,%1,%2,%3};"
        : "+f"(c[0]), "+f"(c[1]), "+f"(c[2]), "+f"(c[3])
        : "r"(a[0]), "r"(a[1]), "r"(a[2]), "r"(a[3]), "r"(b[0]), "r"(b[1]));
}
__device__ __forceinline__ float sigm(float x) { return 1.f / (1.f + expf(-x)); }

// ---------------- prep kernels ----------------
__global__ void prep_bcat(const float* __restrict__ x,
                          const float* __restrict__ Wa1, const float* __restrict__ ba1,
                          const float* __restrict__ Wg1, const float* __restrict__ bg1) {
    __shared__ float xs[DIN];
    int c = threadIdx.x;                    // 256
    for (int k = c; k < DIN; k += 256) xs[k] = x[k];
    __syncthreads();
    const float* W = (c < MW) ? Wa1 : Wg1;
    int cc = c & (MW-1);
    float s = (c < MW) ? ba1[cc] : bg1[cc];
    for (int k = 0; k < DIN; k++) s += xs[k] * W[k*MW + cc];
    g_bcat[c] = s;
}

__global__ void prep_wcat(const float* __restrict__ Wa1, const float* __restrict__ Wg1) {
    int idx = blockIdx.x*256 + threadIdx.x;   // DH*256
    int k = idx >> 8, c = idx & 255;
    float v = (c < MW) ? Wa1[(DIN + k)*MW + c] : Wg1[(DIN + k)*MW + (c - MW)];
    g_WcatH[idx] = __float2half_rn(v);
}

__global__ void prep_w2(const float* __restrict__ Wa2, const float* __restrict__ ba2,
                        const float* __restrict__ Wg2, const float* __restrict__ bg2) {
    int idx = blockIdx.x*256 + threadIdx.x;   // 256*DOUT
    int k = idx >> 9, n = idx & 511;
    float v = (k < MW) ? Wa2[k*DOUT + n] : -Wg2[(k - MW)*DOUT + n];
    g_W2H[idx] = __float2half_rn(v);
    if (idx < DOUT) g_b2[idx] = ba2[idx] - bg2[idx];
    if (idx < 18) g_cnt[idx] = 0;
}

__global__ void prep_wrz(const float* __restrict__ Wih, const float* __restrict__ Whh,
                         const float* __restrict__ bih, const float* __restrict__ bhh) {
    int idx = blockIdx.x*256 + threadIdx.x;   // 1536*2048
    int k = idx >> 11, n = idx & 2047;
    float v = (k < 512) ? Wih[k*H3 + n] : Whh[(k - 512)*H3 + n];
    g_WrzH[idx] = __float2half_rn(v);
    if (idx < 2048) g_brz[idx] = bih[idx] + bhh[idx];
}

__global__ void halfcopy_k(const float* __restrict__ s, __half* __restrict__ d) {
    size_t i = (size_t)blockIdx.x*256 + threadIdx.x;
    float4 v = ((const float4*)s)[i];
    ((__half2*)d)[2*i]   = __floats2half2_rn(v.x, v.y);
    ((__half2*)d)[2*i+1] = __floats2half2_rn(v.z, v.w);
}

__global__ void hid2cat_k(const float* __restrict__ s) {
    size_t i = (size_t)blockIdx.x*256 + threadIdx.x;   // NC*DH/4
    int r = (int)(i >> 8);                              // DH/4 = 256 float4 per row
    int c4 = ((int)i & 255) * 4;
    float4 v = ((const float4*)s)[i];
    __half2* d = (__half2*)&g_catH[(size_t)r*1536 + 512 + c4];
    d[0] = __floats2half2_rn(v.x, v.y);
    d[1] = __floats2half2_rn(v.z, v.w);
}

__global__ void counts_k(const int* __restrict__ pos) {
    __shared__ int s[18];
    int tid = threadIdx.x;                    // 256, grid 64
    if (tid < 18) s[tid] = 0;
    __syncthreads();
    int i = blockIdx.x*256 + tid;
    int p = pos[i], f = i >> 11;
    if (p > 0)      { atomicAdd(&s[0], 1); atomicAdd(&s[2+f], 1); }
    else if (p < 0) { atomicAdd(&s[1], 1); atomicAdd(&s[10+f], 1); }
    __syncthreads();
    if (tid < 18 && s[tid]) atomicAdd(&g_cnt[tid], s[tid]);
}

// ---------------- fp16 mma.sync GEMM, double-buffered, strided operands ----------------
// C[M,N] = A[M,K](lda) @ B[K,N](ldb) + bias[N].  acc fp32.
// 128x128 tile, BK=32, 8 warps 64x32, m16n8k16.
// MODE 0: C fp32 (stride N). MODE 1: relu -> Ch fp16 (stride ldch).
// MODE 2: C fp32 + Ch fp16. MODE 3: fused GRU gate epilogue -> h1out.
#define HTILE 2176                  // 16*136 uint32 per operand per stage
#define HGEMM_SMEM (4*HTILE*4)      // 2 stages * (A+B) = 34816 bytes

template <int MODE>
__global__ __launch_bounds__(256, 2) void hgemm(const __half* __restrict__ A, int lda,
                                                const __half* __restrict__ B, int ldb,
                                                const float* __restrict__ bias,
                                                float* __restrict__ C,
                                                __half* __restrict__ Ch, int ldch,
                                                int N, int K,
                                                const float* __restrict__ Crz,
                                                const float* __restrict__ Gin,
                                                const float* __restrict__ hfull,
                                                const float* __restrict__ wealth,
                                                const float* __restrict__ tens,
                                                const float* __restrict__ WihT,
                                                float* __restrict__ h1out) {
    extern __shared__ uint32_t sm[];
    int tid = threadIdx.x;
    int warp = tid >> 5, lane = tid & 31;
    int go = lane >> 2, tig = lane & 3;
    int wm = warp >> 2, wn = warp & 3;
    const __half* Ab = A + (size_t)(blockIdx.y * 128) * lda;
    const __half* Bb = B + (size_t)blockIdx.x * 128;

    int am = tid & 127;               // A row
    int kh = (tid >> 7) * 16;         // A k offset (0 or 16)
    int br = tid >> 4;                // B pair-row 0..15
    int bc = (tid & 15) * 8;          // B col base

    float acc[4][4][4];
#pragma unroll
    for (int mt = 0; mt < 4; mt++)
#pragma unroll
        for (int nt = 0; nt < 4; nt++)
#pragma unroll
            for (int q = 0; q < 4; q++) acc[mt][nt][q] = 0.f;

    int T = K >> 5;
    uint4 raA0, raA1, rb0, rb1;

#define LDG_TILE(t) do { \
        const __half* ap = Ab + (size_t)am * lda + (t)*32 + kh; \
        raA0 = *(const uint4*)ap; raA1 = *(const uint4*)(ap + 8); \
        const __half* bp = Bb + (size_t)((t)*32 + 2*br) * ldb + bc; \
        rb0 = *(const uint4*)bp; rb1 = *(const uint4*)(bp + ldb); \
    } while (0)

#define STS_TILE(stage) do { \
        uint32_t* As = sm + (stage)*2*HTILE; \
        uint32_t* Bs = As + HTILE; \
        uint32_t w0[8] = {raA0.x, raA0.y, raA0.z, raA0.w, raA1.x, raA1.y, raA1.z, raA1.w}; \
        int kp = kh >> 1; \
        _Pragma("unroll") \
        for (int j = 0; j < 8; j++) As[(kp + j)*136 + am] = w0[j]; \
        uint32_t q0 = __byte_perm(rb0.x, rb1.x, 0x5410), q1 = __byte_perm(rb0.x, rb1.x, 0x7632); \
        uint32_t q2 = __byte_perm(rb0.y, rb1.y, 0x5410), q3 = __byte_perm(rb0.y, rb1.y, 0x7632); \
        uint32_t q4 = __byte_perm(rb0.z, rb1.z, 0x5410), q5 = __byte_perm(rb0.z, rb1.z, 0x7632); \
        uint32_t q6 = __byte_perm(rb0.w, rb1.w, 0x5410), q7 = __byte_perm(rb0.w, rb1.w, 0x7632); \
        *(uint4*)&Bs[br*136 + bc]     = make_uint4(q0, q1, q2, q3); \
        *(uint4*)&Bs[br*136 + bc + 4] = make_uint4(q4, q5, q6, q7); \
    } while (0)

    // prologue
    LDG_TILE(0);
    STS_TILE(0);
    __syncthreads();

    for (int t = 0; t < T; t++) {
        bool more = (t + 1 < T);
        if (more) LDG_TILE(t+1);
        uint32_t* As = sm + (t & 1)*2*HTILE;
        uint32_t* Bs = As + HTILE;
#pragma unroll
        for (int ks = 0; ks < 2; ks++) {
            int kb = ks * 8;
            uint32_t a[4][4], b[4][2];
#pragma unroll
            for (int mt = 0; mt < 4; mt++) {
                int ar = wm*64 + mt*16 + go;
                a[mt][0] = As[(kb + tig)*136 + ar];
                a[mt][1] = As[(kb + tig)*136 + ar + 8];
                a[mt][2] = As[(kb + tig + 4)*136 + ar];
                a[mt][3] = As[(kb + tig + 4)*136 + ar + 8];
            }
#pragma unroll
            for (int nt = 0; nt < 4; nt++) {
                int bq = wn*32 + nt*8 + go;
                b[nt][0] = Bs[(kb + tig)*136 + bq];
                b[nt][1] = Bs[(kb + tig + 4)*136 + bq];
            }
#pragma unroll
            for (int mt = 0; mt < 4; mt++)
#pragma unroll
                for (int nt = 0; nt < 4; nt++)
                    mma16(acc[mt][nt], a[mt], b[nt]);
        }
        if (more) STS_TILE((t+1) & 1);
        __syncthreads();
    }

    // epilogue
#pragma unroll
    for (int mt = 0; mt < 4; mt++) {
        int r0 = blockIdx.y*128 + wm*64 + mt*16 + go;
        float t0, t8, m0, m8;
        if (MODE == 3) {
            t0 = tens[r0]; t8 = tens[r0 + 8];
            float w0 = fminf(fmaxf(wealth[r0], 0.1f), 2.0f);
            float w8 = fminf(fmaxf(wealth[r0 + 8], 0.1f), 2.0f);
            m0 = 0.9f + 0.1f*w0; m8 = 0.9f + 0.1f*w8;
        }
#pragma unroll
        for (int nt = 0; nt < 4; nt++) {
            int c = blockIdx.x*128 + wn*32 + nt*8 + tig*2;
            float b0v = bias[c], b1v = bias[c+1];
            float v0 = acc[mt][nt][0] + b0v;
            float v1 = acc[mt][nt][1] + b1v;
            float v2 = acc[mt][nt][2] + b0v;
            float v3 = acc[mt][nt][3] + b1v;
            if (MODE == 1) {
                v0 = fmaxf(v0, 0.f); v1 = fmaxf(v1, 0.f);
                v2 = fmaxf(v2, 0.f); v3 = fmaxf(v3, 0.f);
                *(__half2*)&Ch[(size_t)r0 * ldch + c]       = __floats2half2_rn(v0, v1);
                *(__half2*)&Ch[(size_t)(r0 + 8) * ldch + c] = __floats2half2_rn(v2, v3);
            } else if (MODE == 2) {
                *(float2*)&C[(size_t)r0 * N + c]            = make_float2(v0, v1);
                *(float2*)&C[(size_t)(r0 + 8) * N + c]      = make_float2(v2, v3);
                *(__half2*)&Ch[(size_t)r0 * ldch + c]       = __floats2half2_rn(v0, v1);
                *(__half2*)&Ch[(size_t)(r0 + 8) * ldch + c] = __floats2half2_rn(v2, v3);
            } else if (MODE == 3) {
                float wr0 = WihT[c],        wr1 = WihT[c+1];
                float wz0 = WihT[DH + c],   wz1 = WihT[DH + c + 1];
                float wn0 = WihT[2*DH + c], wn1 = WihT[2*DH + c + 1];
#pragma unroll
                for (int half = 0; half < 2; half++) {
                    int row = r0 + 8*half;
                    float tt = half ? t8 : t0;
                    float mm = half ? m8 : m0;
                    float g0 = half ? v2 : v0;    // ghn + b_hh_n
                    float g1 = half ? v3 : v1;
                    float2 cr = *(const float2*)&Crz[(size_t)row*2048 + c];
                    float2 cz = *(const float2*)&Crz[(size_t)row*2048 + DH + c];
                    float2 gn = *(const float2*)&Gin[(size_t)row*DH + c];
                    float2 hh = *(const float2*)&hfull[(size_t)row*DH + c];
                    float r_0 = sigm(cr.x + tt*wr0);
                    float r_1 = sigm(cr.y + tt*wr1);
                    float z_0 = sigm(cz.x + tt*wz0);
                    float z_1 = sigm(cz.y + tt*wz1);
                    float n_0 = tanhf(gn.x + tt*wn0 + r_0*g0);
                    float n_1 = tanhf(gn.y + tt*wn1 + r_1*g1);
                    float nh0 = ((1.f - z_0)*n_0 + z_0*hh.x) * mm;
                    float nh1 = ((1.f - z_1)*n_1 + z_1*hh.y) * mm;
                    nh0 = fminf(fmaxf(nh0, -10.f), 10.f);
                    nh1 = fminf(fmaxf(nh1, -10.f), 10.f);
                    *(float2*)&h1out[(size_t)row*DH + c] = make_float2(nh0, nh1);
                }
            } else {
                *(float2*)&C[(size_t)r0 * N + c]       = make_float2(v0, v1);
                *(float2*)&C[(size_t)(r0 + 8) * N + c] = make_float2(v2, v3);
            }
        }
    }
#undef LDG_TILE
#undef STS_TILE
}

// ---------------- tension = mean(output^2, axis=-1) ----------------
__global__ void tension_k() {
    int i = blockIdx.x;
    int tid = threadIdx.x;                    // 128
    const float4* row = (const float4*)(g_out + (size_t)i * DOUT);
    float4 v = row[tid];
    float s = v.x*v.x + v.y*v.y + v.z*v.z + v.w*v.w;
#pragma unroll
    for (int o = 16; o > 0; o >>= 1) s += __shfl_xor_sync(0xffffffffu, s, o);
    __shared__ float ws[4];
    if ((tid & 31) == 0) ws[tid >> 5] = s;
    __syncthreads();
    if (tid == 0) g_tension[i] = (ws[0]+ws[1]+ws[2]+ws[3]) * (1.0f/DOUT);
}

// ---------------- per-column sums ----------------
__global__ void sums1_k(const int* __restrict__ pos) {
    int chunk = blockIdx.x;                   // 64
    int col = blockIdx.y*256 + threadIdx.x;
    float sa = 0.f, sp = 0.f, sn = 0.f;
    int base = chunk * 256;
    for (int r = 0; r < 256; r++) {
        int i = base + r;
        float v = g_h1[(size_t)i*DH + col];
        int p = pos[i];
        sa += v;
        if (p > 0) sp += v;
        else if (p < 0) sn += v;
    }
    g_part_all[chunk*DH + col] = sa;
    g_part_pos[chunk*DH + col] = sp;
    g_part_neg[chunk*DH + col] = sn;
}

__global__ void sums2_k() {
    int col = blockIdx.x*256 + threadIdx.x;
    int cp = g_cnt[0], cn = g_cnt[1];
    bool ap = cp >= 2, an = cn >= 2;
    float psum = 0.f, nsum = 0.f;
    for (int ch = 0; ch < 64; ch++) {
        psum += g_part_pos[ch*DH + col];
        nsum += g_part_neg[ch*DH + col];
    }
    float pm = psum / (float)(cp > 1 ? cp : 1);
    float nm = nsum / (float)(cn > 1 ? cn : 1);
    g_pm[col] = pm; g_nm[col] = nm;
    float gop = 0.f;
    for (int f = 0; f < 8; f++) {
        float a = 0.f, p = 0.f, nn = 0.f;
        for (int c = 0; c < 8; c++) {
            int ch = f*8 + c;
            a  += g_part_all[ch*DH + col];
            p  += g_part_pos[ch*DH + col];
            nn += g_part_neg[ch*DH + col];
        }
        float s = a;
        if (ap) s += -0.1f * p  + 0.1f * (float)g_cnt[2+f]  * pm;
        if (an) s += -0.1f * nn + 0.1f * (float)g_cnt[10+f] * nm;
        float fm = s * (1.f/2048.f);
        g_fmean[f*DH + col] = fm;
        gop += fm;
    }
    g_gop[col] = gop * 0.125f;
}

__global__ void blend_k(const int* __restrict__ pos, const int* __restrict__ step_p,
                        float* __restrict__ outh) {
    int j = blockIdx.x*256 + threadIdx.x;
    int i = blockIdx.y;
    float h2 = g_h1[(size_t)i*DH + j];
    int p = pos[i];
    if (p > 0 && g_cnt[0] >= 2)      h2 = 0.9f*h2 + 0.1f*g_pm[j];
    else if (p < 0 && g_cnt[1] >= 2) h2 = 0.9f*h2 + 0.1f*g_nm[j];
    int f = i >> 11;
    float h3 = 0.85f*h2 + 0.15f*g_fmean[f*DH + j];
    if ((i & 2047) < 512 && step_p[0] > 5) h3 = 0.85f*h3 + 0.15f*g_gop[j];
    outh[(size_t)i*DH + j] = h3;
}

__global__ void smax_k(float* __restrict__ out, int avg_off) {
    int tid = threadIdx.x;                    // 1024
    float m = -3.4e38f;
    for (int i = tid; i < NC; i += 1024) m = fmaxf(m, g_tension[i]);
#pragma unroll
    for (int o = 16; o > 0; o >>= 1) m = fmaxf(m, __shfl_xor_sync(0xffffffffu, m, o));
    __shared__ float red[32];
    if ((tid & 31) == 0) red[tid >> 5] = m;
    __syncthreads();
    if (tid < 32) {
        float v = red[tid];
#pragma unroll
        for (int o = 16; o > 0; o >>= 1) v = fmaxf(v, __shfl_xor_sync(0xffffffffu, v, o));
        if (tid == 0) red[0] = v;
    }
    __syncthreads();
    float mm = red[0];
    __syncthreads();
    float se = 0.f, st = 0.f;
    for (int i = tid; i < NC; i += 1024) {
        float t = g_tension[i];
        st += t;
        float e = expf(t - mm);
        se += e;
        g_wts[i] = e;
    }
#pragma unroll
    for (int o = 16; o > 0; o >>= 1) {
        se += __shfl_xor_sync(0xffffffffu, se, o);
        st += __shfl_xor_sync(0xffffffffu, st, o);
    }
    __shared__ float r2[32], r3[32];
    if ((tid & 31) == 0) { r2[tid >> 5] = se; r3[tid >> 5] = st; }
    __syncthreads();
    if (tid == 0) {
        float a = 0.f, b = 0.f;
        for (int w = 0; w < 32; w++) { a += r2[w]; b += r3[w]; }
        g_soft[0] = mm; g_soft[1] = a;
        out[avg_off] = b * (1.f/NC);
    }
}

__global__ void wsum_k() {
    int j = threadIdx.x;                      // 512
    int b = blockIdx.x;                       // 64
    float s = 0.f;
    int base = b * 256;
    for (int r = 0; r < 256; r++) {
        int i = base + r;
        s += g_wts[i] * g_out[(size_t)i*DOUT + j];
    }
    g_partial[b*DOUT + j] = s;
}

__global__ void pred_k(const float* __restrict__ Wo, const float* __restrict__ bo,
                       float* __restrict__ out) {
    __shared__ float comb[DOUT];
    int j = threadIdx.x;                      // 512
    float s = 0.f;
    for (int b = 0; b < 64; b++) s += g_partial[b*DOUT + j];
    comb[j] = s / g_soft[1];
    __syncthreads();
    float p = bo[j];
    for (int k = 0; k < DOUT; k++) p += comb[k] * Wo[k*DOUT + j];
    out[j] = p;
}

// ---------------- launch ----------------
extern "C" void kernel_launch(void* const* d_in, const int* in_sizes, int n_in,
                              void* d_out, int out_size) {
    const float* x       = (const float*)d_in[0];
    const float* hiddens = (const float*)d_in[1];
    const float* wealth  = (const float*)d_in[2];
    const float* Wa1     = (const float*)d_in[3];
    const float* ba1     = (const float*)d_in[4];
    const float* Wa2     = (const float*)d_in[5];
    const float* ba2     = (const float*)d_in[6];
    const float* Wg1     = (const float*)d_in[7];
    const float* bg1     = (const float*)d_in[8];
    const float* Wg2     = (const float*)d_in[9];
    const float* bg2     = (const float*)d_in[10];
    const float* W_ih    = (const float*)d_in[11];
    const float* W_hh    = (const float*)d_in[12];
    const float* b_ih    = (const float*)d_in[13];
    const float* b_hh    = (const float*)d_in[14];
    const float* Wo      = (const float*)d_in[15];
    const float* bo      = (const float*)d_in[16];
    const int*   pos     = (const int*)d_in[17];
    const int*   step    = (const int*)d_in[18];
    float* out = (float*)d_out;

    size_t newh_off = (size_t)out_size - (size_t)NC * DH;
    int avg_off = (int)(newh_off - 1);

    float *dbcat, *db2, *dbrz, *dOut, *dRz, *dGin, *dTen, *dH1;
    __half *dWcatH, *dW2H, *dWihH, *dWhhH, *dWrzH, *dCatH, *dA1H;
    cudaGetSymbolAddress((void**)&dWcatH, g_WcatH);
    cudaGetSymbolAddress((void**)&dbcat,  g_bcat);
    cudaGetSymbolAddress((void**)&dW2H,   g_W2H);
    cudaGetSymbolAddress((void**)&db2,    g_b2);
    cudaGetSymbolAddress((void**)&dWihH,  g_WihH);
    cudaGetSymbolAddress((void**)&dWhhH,  g_WhhH);
    cudaGetSymbolAddress((void**)&dWrzH,  g_WrzH);
    cudaGetSymbolAddress((void**)&dbrz,   g_brz);
    cudaGetSymbolAddress((void**)&dCatH,  g_catH);
    cudaGetSymbolAddress((void**)&dA1H,   g_A1H);
    cudaGetSymbolAddress((void**)&dOut,   g_out);
    cudaGetSymbolAddress((void**)&dRz,    g_rz);
    cudaGetSymbolAddress((void**)&dGin,   g_gin);
    cudaGetSymbolAddress((void**)&dTen,   g_tension);
    cudaGetSymbolAddress((void**)&dH1,    g_h1);

    // prep (convert everything to fp16 once)
    prep_bcat<<<1, 256>>>(x, Wa1, ba1, Wg1, bg1);
    prep_wcat<<<(DH*256)/256, 256>>>(Wa1, Wg1);
    prep_w2<<<(256*DOUT)/256, 256>>>(Wa2, ba2, Wg2, bg2);
    counts_k<<<64, 256>>>(pos);
    halfcopy_k<<<(DOUT*H3/4)/256, 256>>>(W_ih, dWihH);       // rows 0..511 of W_ih
    halfcopy_k<<<(DH*H3/4)/256, 256>>>(W_hh, dWhhH);
    prep_wrz<<<(1536*2048)/256, 256>>>(W_ih, W_hh, b_ih, b_hh);
    hid2cat_k<<<(int)(((size_t)NC*DH/4)/256), 256>>>(hiddens);

    // G1: A1H = fp16(relu(hH @ WcatH + bcat))   [16384, 256]
    hgemm<1><<<dim3(2, NC/128), 256, HGEMM_SMEM>>>(
        dCatH + 512, 1536, dWcatH, 256, dbcat, nullptr, dA1H, 256, 256, DH,
        nullptr, nullptr, nullptr, nullptr, nullptr, nullptr, nullptr);
    // G2: out = A1H @ W2H + b2   [16384, 512]  fp32 exact + fp16 into catH cols 0..511
    hgemm<2><<<dim3(DOUT/128, NC/128), 256, HGEMM_SMEM>>>(
        dA1H, 256, dW2H, 512, db2, dOut, dCatH, 1536, DOUT, 256,
        nullptr, nullptr, nullptr, nullptr, nullptr, nullptr, nullptr);
    // tension
    tension_k<<<NC, 128>>>();
    // RZ: rz = cat @ WrzH + brz   [16384, 2048]   (gi_rz + gh_rz fused)
    hgemm<0><<<dim3(2048/128, NC/128), 256, HGEMM_SMEM>>>(
        dCatH, 1536, dWrzH, 2048, dbrz, dRz, nullptr, 0, 2048, 1536,
        nullptr, nullptr, nullptr, nullptr, nullptr, nullptr, nullptr);
    // GIN: gin = outH @ Wih_n + b_ih_n   [16384, 1024]
    hgemm<0><<<dim3(DH/128, NC/128), 256, HGEMM_SMEM>>>(
        dCatH, 1536, dWihH + 2048, H3, b_ih + 2048, dGin, nullptr, 0, DH, DOUT,
        nullptr, nullptr, nullptr, nullptr, nullptr, nullptr, nullptr);
    // GHN: ghn = hH @ Whh_n + b_hh_n, fused GRU gate epilogue -> h1
    hgemm<3><<<dim3(DH/128, NC/128), 256, HGEMM_SMEM>>>(
        dCatH + 512, 1536, dWhhH + 2048, H3, b_hh + 2048, nullptr, nullptr, 0, DH, DH,
        dRz, dGin, hiddens, wealth, dTen, W_ih + (size_t)DIN*H3, dH1);
    // sync reductions
    sums1_k<<<dim3(64, DH/256), 256>>>(pos);
    sums2_k<<<DH/256, 256>>>();
    // final blend -> new_h
    blend_k<<<dim3(DH/256, NC), 256>>>(pos, step, out + newh_off);
    // softmax + weighted combine + pred
    smax_k<<<1, 1024>>>(out, avg_off);
    wsum_k<<<64, DOUT>>>();
    pred_k<<<1, DOUT>>>(Wo, bo, out);
}